// round 5
// baseline (speedup 1.0000x reference)
#include <cuda_runtime.h>
#include <math.h>

// ---------------- problem constants ----------------
#define BB   2
#define TT   2048
#define HH   16
#define SS   64
#define EMB  1024          // HH*SS
#define ROWS (BB*TT)       // 4096
#define FF4  (4*EMB)       // 4096

// ---------------- scratch (device globals; no allocation) ----------------
__device__ float g_kqv[(long long)ROWS * HH * 192]; // [B,T,H,192]  (k|q|v)
__device__ float g_res[(long long)ROWS * EMB];      // attention output
__device__ float g_mha[(long long)ROWS * EMB];      // res @ Wproj
__device__ float g_x1 [(long long)ROWS * EMB];      // LN1 output
__device__ float g_h  [(long long)ROWS * FF4];      // gelu(x1@W1+b)
__device__ float g_ff [(long long)ROWS * EMB];      // h@W2+b

// ---------------- generic 64x64x16 SGEMM, EPI: 0=none 1=bias 2=bias+gelu ----
__device__ __forceinline__ float gelu_exact(float v) {
    return 0.5f * v * (1.0f + erff(v * 0.70710678118654752440f));
}

template<int EPI>
__global__ __launch_bounds__(256)
void sgemm64(const float* __restrict__ A, const float* __restrict__ B,
             const float* __restrict__ bias, float* __restrict__ C,
             int M, int N, int K)
{
    __shared__ float As[16][64];   // A transposed: As[k][m]
    __shared__ float Bs[16][64];   // Bs[k][n]

    const int tid = threadIdx.x;
    const int tx  = tid & 15;      // n-sub (x4)
    const int ty  = tid >> 4;      // m-sub (x4)
    const int m0  = blockIdx.y * 64;
    const int n0  = blockIdx.x * 64;

    float acc[4][4];
    #pragma unroll
    for (int i = 0; i < 4; i++)
        #pragma unroll
        for (int j = 0; j < 4; j++) acc[i][j] = 0.f;

    const int lm = tid >> 2;            // 0..63  (A-load row)
    const int lk = (tid & 3) * 4;       // 0,4,8,12
    const int bk = tid >> 4;            // 0..15  (B-load k)
    const int bn = (tid & 15) * 4;      // 0..60

    for (int k0 = 0; k0 < K; k0 += 16) {
        // load A tile (transpose into As)
        {
            float4 a = *(const float4*)(A + (long long)(m0 + lm) * K + k0 + lk);
            As[lk + 0][lm] = a.x;
            As[lk + 1][lm] = a.y;
            As[lk + 2][lm] = a.z;
            As[lk + 3][lm] = a.w;
        }
        // load B tile
        {
            *(float4*)&Bs[bk][bn] =
                *(const float4*)(B + (long long)(k0 + bk) * N + n0 + bn);
        }
        __syncthreads();

        #pragma unroll
        for (int k = 0; k < 16; k++) {
            float4 a4 = *(const float4*)&As[k][ty * 4];
            float4 b4 = *(const float4*)&Bs[k][tx * 4];
            float av[4] = {a4.x, a4.y, a4.z, a4.w};
            float bv[4] = {b4.x, b4.y, b4.z, b4.w};
            #pragma unroll
            for (int i = 0; i < 4; i++)
                #pragma unroll
                for (int j = 0; j < 4; j++)
                    acc[i][j] = fmaf(av[i], bv[j], acc[i][j]);
        }
        __syncthreads();
    }

    float bvv[4] = {0.f, 0.f, 0.f, 0.f};
    if (EPI >= 1) {
        float4 b4 = *(const float4*)(bias + n0 + tx * 4);
        bvv[0] = b4.x; bvv[1] = b4.y; bvv[2] = b4.z; bvv[3] = b4.w;
    }

    #pragma unroll
    for (int i = 0; i < 4; i++) {
        int row = m0 + ty * 4 + i;
        float o[4];
        #pragma unroll
        for (int j = 0; j < 4; j++) {
            float v = acc[i][j];
            if (EPI >= 1) v += bvv[j];
            if (EPI == 2) v = gelu_exact(v);
            o[j] = v;
        }
        *(float4*)(C + (long long)row * N + n0 + tx * 4) =
            make_float4(o[0], o[1], o[2], o[3]);
    }
}

// ---------------- flash attention (fp32) -------------------------------
// grid: (T/64, H, B), block: 64 threads; thread = one query row.
__global__ __launch_bounds__(64)
void attn_kernel(const float* __restrict__ kqv, float* __restrict__ res)
{
    __shared__ float Ks[64][64];
    __shared__ float Vs[64][64];

    const int tid = threadIdx.x;
    const int b   = blockIdx.z;
    const int h   = blockIdx.y;
    const int qi  = blockIdx.x * 64 + tid;

    // load this thread's query (d = 64..127 within the 192-wide kqv row)
    float q[64];
    {
        const float* qp = kqv + (((long long)(b * TT + qi) * HH + h) * 192) + 64;
        #pragma unroll
        for (int k4 = 0; k4 < 16; k4++) {
            float4 t = *(const float4*)(qp + k4 * 4);
            q[k4*4+0] = t.x; q[k4*4+1] = t.y; q[k4*4+2] = t.z; q[k4*4+3] = t.w;
        }
    }

    float acc[64];
    #pragma unroll
    for (int k = 0; k < 64; k++) acc[k] = 0.f;
    float m = -1e30f, l = 0.f;

    for (int j0 = 0; j0 < TT; j0 += 64) {
        // cooperative K/V tile load: thread tid loads key row (j0+tid)
        {
            const float* kp = kqv + (((long long)(b * TT + j0 + tid) * HH + h) * 192);
            #pragma unroll
            for (int k4 = 0; k4 < 16; k4++) {
                *(float4*)&Ks[tid][k4 * 4] = *(const float4*)(kp + k4 * 4);        // k
                *(float4*)&Vs[tid][k4 * 4] = *(const float4*)(kp + 128 + k4 * 4);  // v
            }
        }
        __syncthreads();

        #pragma unroll 1
        for (int jc = 0; jc < 64; jc += 16) {
            float s[16];
            float cmax = -1e30f;
            #pragma unroll
            for (int jj = 0; jj < 16; jj++) {
                const float4* kr = (const float4*)Ks[jc + jj];
                float d = 0.f;
                #pragma unroll
                for (int k4 = 0; k4 < 16; k4++) {
                    float4 kv = kr[k4];
                    d = fmaf(q[k4*4+0], kv.x, d);
                    d = fmaf(q[k4*4+1], kv.y, d);
                    d = fmaf(q[k4*4+2], kv.z, d);
                    d = fmaf(q[k4*4+3], kv.w, d);
                }
                s[jj] = d * 0.125f;
                cmax  = fmaxf(cmax, s[jj]);
            }
            float newm = fmaxf(m, cmax);
            float corr = __expf(m - newm);
            l *= corr;
            #pragma unroll
            for (int k = 0; k < 64; k++) acc[k] *= corr;
            #pragma unroll
            for (int jj = 0; jj < 16; jj++) {
                float p = __expf(s[jj] - newm);
                l += p;
                const float4* vr = (const float4*)Vs[jc + jj];
                #pragma unroll
                for (int k4 = 0; k4 < 16; k4++) {
                    float4 vv = vr[k4];
                    acc[k4*4+0] = fmaf(p, vv.x, acc[k4*4+0]);
                    acc[k4*4+1] = fmaf(p, vv.y, acc[k4*4+1]);
                    acc[k4*4+2] = fmaf(p, vv.z, acc[k4*4+2]);
                    acc[k4*4+3] = fmaf(p, vv.w, acc[k4*4+3]);
                }
            }
            m = newm;
        }
        __syncthreads();
    }

    const float inv = 1.f / l;
    float* op = res + ((long long)(b * TT + qi) * EMB) + h * SS;
    #pragma unroll
    for (int k4 = 0; k4 < 16; k4++) {
        *(float4*)(op + k4 * 4) = make_float4(acc[k4*4+0]*inv, acc[k4*4+1]*inv,
                                              acc[k4*4+2]*inv, acc[k4*4+3]*inv);
    }
}

// ---------------- fused residual + LayerNorm ---------------------------
// out[row] = LN(X[row] + Y[row]) * g + b   ; one block per row, 256 threads
__global__ __launch_bounds__(256)
void ln_kernel(const float* __restrict__ X, const float* __restrict__ Y,
               const float* __restrict__ g, const float* __restrict__ bta,
               float* __restrict__ out)
{
    const int row = blockIdx.x;
    const int tid = threadIdx.x;
    const float* xr = X + (long long)row * EMB;
    const float* yr = Y + (long long)row * EMB;

    float v[4], s = 0.f, ss = 0.f;
    #pragma unroll
    for (int i = 0; i < 4; i++) {
        int c = tid + i * 256;
        float t = xr[c] + yr[c];
        v[i] = t;
        s += t;
        ss = fmaf(t, t, ss);
    }

    __shared__ float rs[8], rss[8];
    #pragma unroll
    for (int o = 16; o > 0; o >>= 1) {
        s  += __shfl_xor_sync(0xffffffffu, s,  o);
        ss += __shfl_xor_sync(0xffffffffu, ss, o);
    }
    const int warp = tid >> 5, lane = tid & 31;
    if (lane == 0) { rs[warp] = s; rss[warp] = ss; }
    __syncthreads();
    float ts = 0.f, tss = 0.f;
    #pragma unroll
    for (int i = 0; i < 8; i++) { ts += rs[i]; tss += rss[i]; }

    const float mean = ts * (1.0f / EMB);
    const float var  = tss * (1.0f / EMB) - mean * mean;
    const float rstd = rsqrtf(var + 1e-5f);

    #pragma unroll
    for (int i = 0; i < 4; i++) {
        int c = tid + i * 256;
        out[(long long)row * EMB + c] = (v[i] - mean) * rstd * g[c] + bta[c];
    }
}

// ---------------- launch --------------------------------------------------
extern "C" void kernel_launch(void* const* d_in, const int* in_sizes, int n_in,
                              void* d_out, int out_size)
{
    const float* x     = (const float*)d_in[0];
    const float* Wkqv  = (const float*)d_in[1];
    const float* Wproj = (const float*)d_in[2];
    const float* g1    = (const float*)d_in[3];
    const float* b1    = (const float*)d_in[4];
    const float* W1    = (const float*)d_in[5];
    const float* bff1  = (const float*)d_in[6];
    const float* W2    = (const float*)d_in[7];
    const float* bff2  = (const float*)d_in[8];
    const float* g2    = (const float*)d_in[9];
    const float* b2    = (const float*)d_in[10];
    float* out = (float*)d_out;

    float *p_kqv, *p_res, *p_mha, *p_x1, *p_h, *p_ff;
    cudaGetSymbolAddress((void**)&p_kqv, g_kqv);
    cudaGetSymbolAddress((void**)&p_res, g_res);
    cudaGetSymbolAddress((void**)&p_mha, g_mha);
    cudaGetSymbolAddress((void**)&p_x1,  g_x1);
    cudaGetSymbolAddress((void**)&p_h,   g_h);
    cudaGetSymbolAddress((void**)&p_ff,  g_ff);

    // 1) kqv = xh @ Wkqv   : [65536,64] @ [64,192]
    sgemm64<0><<<dim3(192/64, (ROWS*HH)/64), 256>>>(x, Wkqv, nullptr, p_kqv,
                                                    ROWS*HH, 192, SS);
    // 2) attention
    attn_kernel<<<dim3(TT/64, HH, BB), 64>>>(p_kqv, p_res);
    // 3) mha = res @ Wproj : [4096,1024] @ [1024,1024]
    sgemm64<0><<<dim3(EMB/64, ROWS/64), 256>>>(p_res, Wproj, nullptr, p_mha,
                                               ROWS, EMB, EMB);
    // 4) x1 = LN(x + mha)
    ln_kernel<<<ROWS, 256>>>(x, p_mha, g1, b1, p_x1);
    // 5) h = gelu(x1 @ W1 + bff1) : [4096,1024] @ [1024,4096]
    sgemm64<2><<<dim3(FF4/64, ROWS/64), 256>>>(p_x1, W1, bff1, p_h,
                                               ROWS, FF4, EMB);
    // 6) ff = h @ W2 + bff2 : [4096,4096] @ [4096,1024]
    sgemm64<1><<<dim3(EMB/64, ROWS/64), 256>>>(p_h, W2, bff2, p_ff,
                                               ROWS, EMB, FF4);
    // 7) out = LN(x1 + ff)
    ln_kernel<<<ROWS, 256>>>(p_x1, p_ff, g2, b2, out);
}

// round 6
// speedup vs baseline: 3.9229x; 3.9229x over previous
#include <cuda_runtime.h>
#include <math.h>
#include <stdint.h>

// ---------------- problem constants ----------------
#define BB   2
#define TT   2048
#define HH   16
#define SS   64
#define EMB  1024          // HH*SS
#define ROWS (BB*TT)       // 4096
#define FF4  (4*EMB)       // 4096

// ---------------- scratch (device globals; no allocation) ----------------
__device__ float g_kqv[(long long)ROWS * HH * 192]; // [B,T,H,192]  (k|q|v)
__device__ float g_res[(long long)ROWS * EMB];      // attention output
__device__ float g_mha[(long long)ROWS * EMB];      // res @ Wproj
__device__ float g_x1 [(long long)ROWS * EMB];      // LN1 output
__device__ float g_h  [(long long)ROWS * FF4];      // gelu(x1@W1+b)
__device__ float g_ff [(long long)ROWS * EMB];      // h@W2+b

// ---------------- helpers ----------------
__device__ __forceinline__ float gelu_exact(float v) {
    return 0.5f * v * (1.0f + erff(v * 0.70710678118654752440f));
}

// round-to-nearest f32 -> tf32 (bits in a b32 reg). RNA, not truncation:
// truncation is a biased error (~2^-10) that does NOT cancel over the K-sum.
__device__ __forceinline__ uint32_t f2tf(float x) {
    uint32_t r;
    asm("cvt.rna.tf32.f32 %0, %1;" : "=r"(r) : "f"(x));
    return r;
}

__device__ __forceinline__ void mma_tf32(float (&d)[4], const uint32_t (&a)[4],
                                         const uint32_t (&b)[2], const float (&c)[4]) {
    asm volatile(
        "mma.sync.aligned.m16n8k8.row.col.f32.tf32.tf32.f32 "
        "{%0,%1,%2,%3}, {%4,%5,%6,%7}, {%8,%9}, {%10,%11,%12,%13};\n"
        : "=f"(d[0]), "=f"(d[1]), "=f"(d[2]), "=f"(d[3])
        : "r"(a[0]), "r"(a[1]), "r"(a[2]), "r"(a[3]),
          "r"(b[0]), "r"(b[1]),
          "f"(c[0]), "f"(c[1]), "f"(c[2]), "f"(c[3]));
}

// ================= tf32 tensor-core GEMM =================
// C[M,N] = A[M,K] @ B[K,N] (+bias)(+gelu). BM=128, BK=32, BN template (128 or 64).
// 256 threads = 8 warps in 4(m) x 2(n); warp tile = 32 x (BN/2).
template<int BN, int EPI>
__global__ __launch_bounds__(256)
void gemm_tf32(const float* __restrict__ A, const float* __restrict__ B,
               const float* __restrict__ bias, float* __restrict__ C,
               int M, int N, int K)
{
    constexpr int BM = 128, BK = 32;
    constexpr int WN  = BN / 2;              // warp n-extent
    constexpr int NT  = WN / 8;              // n-tiles (n8) per warp
    constexpr int NA4 = 4;                   // A float4 loads / thread
    constexpr int NB4 = (BK * BN) / (4 * 256);
    constexpr int BROW = BN / 4;             // float4 per B row

    __shared__ uint32_t As[BM][BK + 4];      // padded: conflict-free frag LDS
    __shared__ uint32_t Bs[BK][BN + 4];

    const int tid  = threadIdx.x;
    const int w    = tid >> 5;
    const int lane = tid & 31;
    const int g    = lane >> 2;
    const int t4   = lane & 3;
    const int wm   = w >> 1;                 // 0..3
    const int wn   = w & 1;                  // 0..1
    const int m0   = blockIdx.y * BM;
    const int n0   = blockIdx.x * BN;

    float acc[2][NT][4];
    #pragma unroll
    for (int mt = 0; mt < 2; mt++)
        #pragma unroll
        for (int nt = 0; nt < NT; nt++)
            #pragma unroll
            for (int i = 0; i < 4; i++) acc[mt][nt][i] = 0.f;

    float4 pa[NA4], pb[NB4];
    // prefetch tile k0 = 0
    #pragma unroll
    for (int i = 0; i < NA4; i++) {
        int fi = tid + i * 256;              // 0..1023
        int r = fi >> 3, c = (fi & 7) * 4;
        pa[i] = *(const float4*)(A + (long long)(m0 + r) * K + c);
    }
    #pragma unroll
    for (int i = 0; i < NB4; i++) {
        int fi = tid + i * 256;
        int r = fi / BROW, c = (fi % BROW) * 4;
        pb[i] = *(const float4*)(B + (long long)r * N + n0 + c);
    }

    for (int k0 = 0; k0 < K; k0 += BK) {
        // commit prefetched tile to smem (tf32-rounded)
        #pragma unroll
        for (int i = 0; i < NA4; i++) {
            int fi = tid + i * 256;
            int r = fi >> 3, c = (fi & 7) * 4;
            As[r][c + 0] = f2tf(pa[i].x); As[r][c + 1] = f2tf(pa[i].y);
            As[r][c + 2] = f2tf(pa[i].z); As[r][c + 3] = f2tf(pa[i].w);
        }
        #pragma unroll
        for (int i = 0; i < NB4; i++) {
            int fi = tid + i * 256;
            int r = fi / BROW, c = (fi % BROW) * 4;
            Bs[r][c + 0] = f2tf(pb[i].x); Bs[r][c + 1] = f2tf(pb[i].y);
            Bs[r][c + 2] = f2tf(pb[i].z); Bs[r][c + 3] = f2tf(pb[i].w);
        }
        __syncthreads();

        // prefetch next tile into registers (overlaps the mma block)
        if (k0 + BK < K) {
            #pragma unroll
            for (int i = 0; i < NA4; i++) {
                int fi = tid + i * 256;
                int r = fi >> 3, c = (fi & 7) * 4;
                pa[i] = *(const float4*)(A + (long long)(m0 + r) * K + (k0 + BK) + c);
            }
            #pragma unroll
            for (int i = 0; i < NB4; i++) {
                int fi = tid + i * 256;
                int r = fi / BROW, c = (fi % BROW) * 4;
                pb[i] = *(const float4*)(B + (long long)(k0 + BK + r) * N + n0 + c);
            }
        }

        #pragma unroll
        for (int kk = 0; kk < 4; kk++) {
            uint32_t a[2][4];
            #pragma unroll
            for (int mt = 0; mt < 2; mt++) {
                int rm = wm * 32 + mt * 16;
                a[mt][0] = As[rm + g    ][kk * 8 + t4];
                a[mt][1] = As[rm + g + 8][kk * 8 + t4];
                a[mt][2] = As[rm + g    ][kk * 8 + t4 + 4];
                a[mt][3] = As[rm + g + 8][kk * 8 + t4 + 4];
            }
            #pragma unroll
            for (int nt = 0; nt < NT; nt++) {
                uint32_t b[2];
                b[0] = Bs[kk * 8 + t4    ][wn * WN + nt * 8 + g];
                b[1] = Bs[kk * 8 + t4 + 4][wn * WN + nt * 8 + g];
                mma_tf32(acc[0][nt], a[0], b, acc[0][nt]);
                mma_tf32(acc[1][nt], a[1], b, acc[1][nt]);
            }
        }
        __syncthreads();
    }

    // epilogue: each thread owns (rows g, g+8) x (cols 2*t4, 2*t4+1) per tile
    #pragma unroll
    for (int mt = 0; mt < 2; mt++) {
        int row = m0 + wm * 32 + mt * 16 + g;
        #pragma unroll
        for (int nt = 0; nt < NT; nt++) {
            int col = n0 + wn * WN + nt * 8 + 2 * t4;
            float v00 = acc[mt][nt][0], v01 = acc[mt][nt][1];
            float v10 = acc[mt][nt][2], v11 = acc[mt][nt][3];
            if (EPI >= 1) {
                float b0 = bias[col], b1 = bias[col + 1];
                v00 += b0; v01 += b1; v10 += b0; v11 += b1;
            }
            if (EPI == 2) {
                v00 = gelu_exact(v00); v01 = gelu_exact(v01);
                v10 = gelu_exact(v10); v11 = gelu_exact(v11);
            }
            *(float2*)(C + (long long)row * N + col)       = make_float2(v00, v01);
            *(float2*)(C + (long long)(row + 8) * N + col) = make_float2(v10, v11);
        }
    }
}

// ================= tensor-core flash attention =================
// grid (T/64, H, B), 128 threads = 4 warps; warp w owns query rows [q0, q0+16).
// S=64 head dim. K/V tiles of 64 keys in smem (tf32), P staged via per-warp smem.
__global__ __launch_bounds__(128)
void attn_mma(const float* __restrict__ kqv, float* __restrict__ res)
{
    extern __shared__ uint32_t dsm[];
    uint32_t* Ks = dsm;                      // [64][68]
    uint32_t* Vs = dsm + 64 * 68;            // [64][68]
    uint32_t* Ps = dsm + 2 * 64 * 68;        // [4][16][68]

    const int tid  = threadIdx.x;
    const int w    = tid >> 5;
    const int lane = tid & 31;
    const int g    = lane >> 2;
    const int t4   = lane & 3;
    const int b    = blockIdx.z;
    const int h    = blockIdx.y;
    const int q0   = blockIdx.x * 64 + w * 16;

    const long long rowstride = (long long)HH * 192;
    const float* base = kqv + ((long long)b * TT * HH + h) * 192;

    // Q fragments: rows (q0+g, q0+8+g), cols kk*8+t4 (+4); q at offset 64
    uint32_t qf[8][4];
    {
        const float* qp0 = base + (long long)(q0 + g)     * rowstride + 64;
        const float* qp1 = base + (long long)(q0 + 8 + g) * rowstride + 64;
        #pragma unroll
        for (int kk = 0; kk < 8; kk++) {
            qf[kk][0] = f2tf(qp0[kk * 8 + t4]);
            qf[kk][1] = f2tf(qp1[kk * 8 + t4]);
            qf[kk][2] = f2tf(qp0[kk * 8 + t4 + 4]);
            qf[kk][3] = f2tf(qp1[kk * 8 + t4 + 4]);
        }
    }

    float acc[8][4];
    #pragma unroll
    for (int nt = 0; nt < 8; nt++)
        #pragma unroll
        for (int i = 0; i < 4; i++) acc[nt][i] = 0.f;
    float m0v = -1e30f, m1v = -1e30f, l0 = 0.f, l1 = 0.f;

    for (int j0 = 0; j0 < TT; j0 += 64) {
        // cooperative K/V tile load (tf32-rounded)
        #pragma unroll
        for (int i = 0; i < 8; i++) {
            int fi = tid + i * 128;          // 0..1023
            int r = fi >> 4, c = (fi & 15) * 4;
            const float* kp = base + (long long)(j0 + r) * rowstride;
            float4 kv = *(const float4*)(kp + c);          // k at offset 0
            float4 vv = *(const float4*)(kp + 128 + c);    // v at offset 128
            Ks[r * 68 + c + 0] = f2tf(kv.x); Ks[r * 68 + c + 1] = f2tf(kv.y);
            Ks[r * 68 + c + 2] = f2tf(kv.z); Ks[r * 68 + c + 3] = f2tf(kv.w);
            Vs[r * 68 + c + 0] = f2tf(vv.x); Vs[r * 68 + c + 1] = f2tf(vv.y);
            Vs[r * 68 + c + 2] = f2tf(vv.z); Vs[r * 68 + c + 3] = f2tf(vv.w);
        }
        __syncthreads();

        // S = Q @ K^T  (B frag: K^T[k][n] = Ks[key=n][dim=k])
        float s[8][4];
        #pragma unroll
        for (int nt = 0; nt < 8; nt++) {
            s[nt][0] = s[nt][1] = s[nt][2] = s[nt][3] = 0.f;
            #pragma unroll
            for (int kk = 0; kk < 8; kk++) {
                uint32_t bb[2];
                bb[0] = Ks[(nt * 8 + g) * 68 + kk * 8 + t4];
                bb[1] = Ks[(nt * 8 + g) * 68 + kk * 8 + t4 + 4];
                mma_tf32(s[nt], qf[kk], bb, s[nt]);
            }
        }

        // online softmax (rows g and g+8 per thread; quad = lanes sharing g)
        float rmax0 = -1e30f, rmax1 = -1e30f;
        #pragma unroll
        for (int nt = 0; nt < 8; nt++) {
            s[nt][0] *= 0.125f; s[nt][1] *= 0.125f;
            s[nt][2] *= 0.125f; s[nt][3] *= 0.125f;
            rmax0 = fmaxf(rmax0, fmaxf(s[nt][0], s[nt][1]));
            rmax1 = fmaxf(rmax1, fmaxf(s[nt][2], s[nt][3]));
        }
        rmax0 = fmaxf(rmax0, __shfl_xor_sync(0xffffffffu, rmax0, 1));
        rmax0 = fmaxf(rmax0, __shfl_xor_sync(0xffffffffu, rmax0, 2));
        rmax1 = fmaxf(rmax1, __shfl_xor_sync(0xffffffffu, rmax1, 1));
        rmax1 = fmaxf(rmax1, __shfl_xor_sync(0xffffffffu, rmax1, 2));

        float mn0 = fmaxf(m0v, rmax0), mn1 = fmaxf(m1v, rmax1);
        float c0 = __expf(m0v - mn0), c1 = __expf(m1v - mn1);
        m0v = mn0; m1v = mn1;

        float ps0 = 0.f, ps1 = 0.f;
        #pragma unroll
        for (int nt = 0; nt < 8; nt++) {
            s[nt][0] = __expf(s[nt][0] - mn0); ps0 += s[nt][0];
            s[nt][1] = __expf(s[nt][1] - mn0); ps0 += s[nt][1];
            s[nt][2] = __expf(s[nt][2] - mn1); ps1 += s[nt][2];
            s[nt][3] = __expf(s[nt][3] - mn1); ps1 += s[nt][3];
        }
        ps0 += __shfl_xor_sync(0xffffffffu, ps0, 1);
        ps0 += __shfl_xor_sync(0xffffffffu, ps0, 2);
        ps1 += __shfl_xor_sync(0xffffffffu, ps1, 1);
        ps1 += __shfl_xor_sync(0xffffffffu, ps1, 2);
        l0 = l0 * c0 + ps0;
        l1 = l1 * c1 + ps1;

        // rescale accumulators
        #pragma unroll
        for (int nt = 0; nt < 8; nt++) {
            acc[nt][0] *= c0; acc[nt][1] *= c0;
            acc[nt][2] *= c1; acc[nt][3] *= c1;
        }

        // stage P (C-frag layout) through per-warp smem, reload as A-frags
        uint32_t* Pw = Ps + w * 16 * 68;
        __syncwarp();
        #pragma unroll
        for (int nt = 0; nt < 8; nt++) {
            Pw[g * 68 + nt * 8 + 2 * t4]           = f2tf(s[nt][0]);
            Pw[g * 68 + nt * 8 + 2 * t4 + 1]       = f2tf(s[nt][1]);
            Pw[(g + 8) * 68 + nt * 8 + 2 * t4]     = f2tf(s[nt][2]);
            Pw[(g + 8) * 68 + nt * 8 + 2 * t4 + 1] = f2tf(s[nt][3]);
        }
        __syncwarp();
        uint32_t af[8][4];
        #pragma unroll
        for (int kk = 0; kk < 8; kk++) {
            af[kk][0] = Pw[g * 68 + kk * 8 + t4];
            af[kk][1] = Pw[(g + 8) * 68 + kk * 8 + t4];
            af[kk][2] = Pw[g * 68 + kk * 8 + t4 + 4];
            af[kk][3] = Pw[(g + 8) * 68 + kk * 8 + t4 + 4];
        }

        // acc += P @ V   (B frag: V[k=key][n=dim] = Vs[key][dim])
        #pragma unroll
        for (int nt = 0; nt < 8; nt++) {
            #pragma unroll
            for (int kk = 0; kk < 8; kk++) {
                uint32_t bb[2];
                bb[0] = Vs[(kk * 8 + t4) * 68 + nt * 8 + g];
                bb[1] = Vs[(kk * 8 + t4 + 4) * 68 + nt * 8 + g];
                mma_tf32(acc[nt], af[kk], bb, acc[nt]);
            }
        }
        __syncthreads();
    }

    const float inv0 = 1.f / l0, inv1 = 1.f / l1;
    float* o0 = res + (long long)(b * TT + q0 + g) * EMB + h * SS;
    float* o1 = res + (long long)(b * TT + q0 + 8 + g) * EMB + h * SS;
    #pragma unroll
    for (int nt = 0; nt < 8; nt++) {
        *(float2*)(o0 + nt * 8 + 2 * t4) = make_float2(acc[nt][0] * inv0, acc[nt][1] * inv0);
        *(float2*)(o1 + nt * 8 + 2 * t4) = make_float2(acc[nt][2] * inv1, acc[nt][3] * inv1);
    }
}

// ---------------- fused residual + LayerNorm ---------------------------
__global__ __launch_bounds__(256)
void ln_kernel(const float* __restrict__ X, const float* __restrict__ Y,
               const float* __restrict__ g, const float* __restrict__ bta,
               float* __restrict__ out)
{
    const int row = blockIdx.x;
    const int tid = threadIdx.x;
    const float* xr = X + (long long)row * EMB;
    const float* yr = Y + (long long)row * EMB;

    float v[4], s = 0.f, ss = 0.f;
    #pragma unroll
    for (int i = 0; i < 4; i++) {
        int c = tid + i * 256;
        float t = xr[c] + yr[c];
        v[i] = t;
        s += t;
        ss = fmaf(t, t, ss);
    }

    __shared__ float rs[8], rss[8];
    #pragma unroll
    for (int o = 16; o > 0; o >>= 1) {
        s  += __shfl_xor_sync(0xffffffffu, s,  o);
        ss += __shfl_xor_sync(0xffffffffu, ss, o);
    }
    const int warp = tid >> 5, lane = tid & 31;
    if (lane == 0) { rs[warp] = s; rss[warp] = ss; }
    __syncthreads();
    float ts = 0.f, tss = 0.f;
    #pragma unroll
    for (int i = 0; i < 8; i++) { ts += rs[i]; tss += rss[i]; }

    const float mean = ts * (1.0f / EMB);
    const float var  = tss * (1.0f / EMB) - mean * mean;
    const float rstd = rsqrtf(var + 1e-5f);

    #pragma unroll
    for (int i = 0; i < 4; i++) {
        int c = tid + i * 256;
        out[(long long)row * EMB + c] = (v[i] - mean) * rstd * g[c] + bta[c];
    }
}

// ---------------- launch --------------------------------------------------
extern "C" void kernel_launch(void* const* d_in, const int* in_sizes, int n_in,
                              void* d_out, int out_size)
{
    const float* x     = (const float*)d_in[0];
    const float* Wkqv  = (const float*)d_in[1];
    const float* Wproj = (const float*)d_in[2];
    const float* g1    = (const float*)d_in[3];
    const float* b1    = (const float*)d_in[4];
    const float* W1    = (const float*)d_in[5];
    const float* bff1  = (const float*)d_in[6];
    const float* W2    = (const float*)d_in[7];
    const float* bff2  = (const float*)d_in[8];
    const float* g2    = (const float*)d_in[9];
    const float* b2    = (const float*)d_in[10];
    float* out = (float*)d_out;

    float *p_kqv, *p_res, *p_mha, *p_x1, *p_h, *p_ff;
    cudaGetSymbolAddress((void**)&p_kqv, g_kqv);
    cudaGetSymbolAddress((void**)&p_res, g_res);
    cudaGetSymbolAddress((void**)&p_mha, g_mha);
    cudaGetSymbolAddress((void**)&p_x1,  g_x1);
    cudaGetSymbolAddress((void**)&p_h,   g_h);
    cudaGetSymbolAddress((void**)&p_ff,  g_ff);

    const int attn_smem = (2 * 64 * 68 + 4 * 16 * 68) * 4;  // 52224 B
    static int attr_set = 0;
    if (!attr_set) {
        cudaFuncSetAttribute(attn_mma, cudaFuncAttributeMaxDynamicSharedMemorySize, 56 * 1024);
        attr_set = 1;
    }

    // 1) kqv = xh @ Wkqv : [65536,64] @ [64,192]
    gemm_tf32<64, 0><<<dim3(192 / 64, (ROWS * HH) / 128), 256>>>(
        x, Wkqv, nullptr, p_kqv, ROWS * HH, 192, SS);
    // 2) attention (tensor-core flash)
    attn_mma<<<dim3(TT / 64, HH, BB), 128, attn_smem>>>(p_kqv, p_res);
    // 3) mha = res @ Wproj : [4096,1024] @ [1024,1024]
    gemm_tf32<128, 0><<<dim3(EMB / 128, ROWS / 128), 256>>>(
        p_res, Wproj, nullptr, p_mha, ROWS, EMB, EMB);
    // 4) x1 = LN(x + mha)
    ln_kernel<<<ROWS, 256>>>(x, p_mha, g1, b1, p_x1);
    // 5) h = gelu(x1 @ W1 + bff1) : [4096,1024] @ [1024,4096]
    gemm_tf32<128, 2><<<dim3(FF4 / 128, ROWS / 128), 256>>>(
        p_x1, W1, bff1, p_h, ROWS, FF4, EMB);
    // 6) ff = h @ W2 + bff2 : [4096,4096] @ [4096,1024]
    gemm_tf32<128, 1><<<dim3(EMB / 128, ROWS / 128), 256>>>(
        p_h, W2, bff2, p_ff, ROWS, EMB, FF4);
    // 7) out = LN(x1 + ff)
    ln_kernel<<<ROWS, 256>>>(p_x1, p_ff, g2, b2, out);
}

// round 8
// speedup vs baseline: 6.1074x; 1.5569x over previous
#include <cuda_runtime.h>
#include <cuda_fp16.h>
#include <math.h>
#include <stdint.h>

// ---------------- problem constants ----------------
#define BB   2
#define TT   2048
#define HH   16
#define SS   64
#define EMB  1024          // HH*SS
#define ROWS (BB*TT)       // 4096
#define FF4  (4*EMB)       // 4096

// ---------------- scratch (device globals; no allocation) ----------------
__device__ __half g_kqv[(long long)ROWS * HH * 192]; // [B,T,H,192] (k|q|v) fp16
__device__ __half g_res[(long long)ROWS * EMB];      // attention out (fp16)
__device__ float  g_mha[(long long)ROWS * EMB];
__device__ float  g_x1 [(long long)ROWS * EMB];
__device__ __half g_x1h[(long long)ROWS * EMB];
__device__ __half g_hh [(long long)ROWS * FF4];
__device__ float  g_ff [(long long)ROWS * EMB];
// transposed fp16 weights: [N, K]
__device__ __half g_Wkt[(long long)192 * SS];
__device__ __half g_Wpt[(long long)EMB * EMB];
__device__ __half g_W1t[(long long)FF4 * EMB];
__device__ __half g_W2t[(long long)EMB * FF4];

// ---------------- helpers ----------------
__device__ __forceinline__ float gelu_exact(float v) {
    return 0.5f * v * (1.0f + erff(v * 0.70710678118654752440f));
}
__device__ __forceinline__ void mma_f16(float (&d)[4], const uint32_t (&a)[4],
                                        const uint32_t (&b)[2], const float (&c)[4]) {
    asm volatile(
        "mma.sync.aligned.m16n8k16.row.col.f32.f16.f16.f32 "
        "{%0,%1,%2,%3}, {%4,%5,%6,%7}, {%8,%9}, {%10,%11,%12,%13};\n"
        : "=f"(d[0]), "=f"(d[1]), "=f"(d[2]), "=f"(d[3])
        : "r"(a[0]), "r"(a[1]), "r"(a[2]), "r"(a[3]),
          "r"(b[0]), "r"(b[1]),
          "f"(c[0]), "f"(c[1]), "f"(c[2]), "f"(c[3]));
}
__device__ __forceinline__ uint32_t pack2(float lo, float hi) {
    __half2 h = __floats2half2_rn(lo, hi);
    return *(uint32_t*)&h;
}

// ================= fp16 tensor-core GEMM =================
// C[M,N] = A[M,K] @ Bt[N,K]^T.  BM=128, BK=32, BN in {64,128}.
// 256 threads = 8 warps (4m x 2n); warp tile 32 x (BN/2).
// EPI: 0 = f32 store; 1 = +bias f32; 2 = +bias+gelu half; 3 = plain half.
template<int BN, int EPI, bool AF32>
__global__ __launch_bounds__(256)
void gemm_f16(const float* __restrict__ Af, const __half* __restrict__ Ah,
              const __half* __restrict__ Bt, const float* __restrict__ bias,
              float* __restrict__ Cf, __half* __restrict__ Ch,
              int M, int N, int K)
{
    constexpr int BM = 128, BK = 32;
    constexpr int WN  = BN / 2;
    constexpr int NT  = WN / 8;             // n8 tiles per warp
    constexpr int ACH = (BM * BK) / (8 * 256);   // 2
    constexpr int BCH = (BN * BK) / (8 * 256);   // 1 or 2
    constexpr int LDP = 40;                 // padded row stride (halves)

    __shared__ __half As[BM][LDP];
    __shared__ __half Bs[BN][LDP];

    const int tid  = threadIdx.x;
    const int w    = tid >> 5;
    const int lane = tid & 31;
    const int g    = lane >> 2;
    const int t4   = lane & 3;
    const int wm   = w >> 1;
    const int wn   = w & 1;
    const int m0   = blockIdx.y * BM;
    const int n0   = blockIdx.x * BN;

    float acc[2][NT][4];
    #pragma unroll
    for (int mt = 0; mt < 2; mt++)
        #pragma unroll
        for (int nt = 0; nt < NT; nt++)
            #pragma unroll
            for (int i = 0; i < 4; i++) acc[mt][nt][i] = 0.f;

    float4 paf[ACH][2];
    uint4  pah[ACH];
    uint4  pb[BCH];

    // prefetch k0 = 0
    #pragma unroll
    for (int i = 0; i < ACH; i++) {
        int fi = tid + i * 256;
        int r = fi >> 2, c8 = (fi & 3) * 8;
        if (AF32) {
            paf[i][0] = *(const float4*)(Af + (long long)(m0 + r) * K + c8);
            paf[i][1] = *(const float4*)(Af + (long long)(m0 + r) * K + c8 + 4);
        } else {
            pah[i] = *(const uint4*)(Ah + (long long)(m0 + r) * K + c8);
        }
    }
    #pragma unroll
    for (int i = 0; i < BCH; i++) {
        int fi = tid + i * 256;
        int r = fi >> 2, c8 = (fi & 3) * 8;
        pb[i] = *(const uint4*)(Bt + (long long)(n0 + r) * K + c8);
    }

    for (int k0 = 0; k0 < K; k0 += BK) {
        // commit to smem
        #pragma unroll
        for (int i = 0; i < ACH; i++) {
            int fi = tid + i * 256;
            int r = fi >> 2, c8 = (fi & 3) * 8;
            if (AF32) {
                __half h[8];
                h[0] = __float2half_rn(paf[i][0].x); h[1] = __float2half_rn(paf[i][0].y);
                h[2] = __float2half_rn(paf[i][0].z); h[3] = __float2half_rn(paf[i][0].w);
                h[4] = __float2half_rn(paf[i][1].x); h[5] = __float2half_rn(paf[i][1].y);
                h[6] = __float2half_rn(paf[i][1].z); h[7] = __float2half_rn(paf[i][1].w);
                *(uint2*)&As[r][c8]     = *(uint2*)&h[0];
                *(uint2*)&As[r][c8 + 4] = *(uint2*)&h[4];
            } else {
                *(uint2*)&As[r][c8]     = make_uint2(pah[i].x, pah[i].y);
                *(uint2*)&As[r][c8 + 4] = make_uint2(pah[i].z, pah[i].w);
            }
        }
        #pragma unroll
        for (int i = 0; i < BCH; i++) {
            int fi = tid + i * 256;
            int r = fi >> 2, c8 = (fi & 3) * 8;
            *(uint2*)&Bs[r][c8]     = make_uint2(pb[i].x, pb[i].y);
            *(uint2*)&Bs[r][c8 + 4] = make_uint2(pb[i].z, pb[i].w);
        }
        __syncthreads();

        // prefetch next
        if (k0 + BK < K) {
            #pragma unroll
            for (int i = 0; i < ACH; i++) {
                int fi = tid + i * 256;
                int r = fi >> 2, c8 = (fi & 3) * 8;
                if (AF32) {
                    paf[i][0] = *(const float4*)(Af + (long long)(m0 + r) * K + k0 + BK + c8);
                    paf[i][1] = *(const float4*)(Af + (long long)(m0 + r) * K + k0 + BK + c8 + 4);
                } else {
                    pah[i] = *(const uint4*)(Ah + (long long)(m0 + r) * K + k0 + BK + c8);
                }
            }
            #pragma unroll
            for (int i = 0; i < BCH; i++) {
                int fi = tid + i * 256;
                int r = fi >> 2, c8 = (fi & 3) * 8;
                pb[i] = *(const uint4*)(Bt + (long long)(n0 + r) * K + k0 + BK + c8);
            }
        }

        #pragma unroll
        for (int ks = 0; ks < 2; ks++) {
            uint32_t a[2][4];
            #pragma unroll
            for (int mt = 0; mt < 2; mt++) {
                int rm = wm * 32 + mt * 16;
                a[mt][0] = *(uint32_t*)&As[rm + g    ][ks * 16 + 2 * t4];
                a[mt][1] = *(uint32_t*)&As[rm + g + 8][ks * 16 + 2 * t4];
                a[mt][2] = *(uint32_t*)&As[rm + g    ][ks * 16 + 2 * t4 + 8];
                a[mt][3] = *(uint32_t*)&As[rm + g + 8][ks * 16 + 2 * t4 + 8];
            }
            #pragma unroll
            for (int nt = 0; nt < NT; nt++) {
                uint32_t b[2];
                int n = wn * WN + nt * 8 + g;
                b[0] = *(uint32_t*)&Bs[n][ks * 16 + 2 * t4];
                b[1] = *(uint32_t*)&Bs[n][ks * 16 + 2 * t4 + 8];
                mma_f16(acc[0][nt], a[0], b, acc[0][nt]);
                mma_f16(acc[1][nt], a[1], b, acc[1][nt]);
            }
        }
        __syncthreads();
    }

    // epilogue
    #pragma unroll
    for (int mt = 0; mt < 2; mt++) {
        int row = m0 + wm * 32 + mt * 16 + g;
        #pragma unroll
        for (int nt = 0; nt < NT; nt++) {
            int col = n0 + wn * WN + nt * 8 + 2 * t4;
            float v00 = acc[mt][nt][0], v01 = acc[mt][nt][1];
            float v10 = acc[mt][nt][2], v11 = acc[mt][nt][3];
            if (EPI == 1 || EPI == 2) {
                float b0 = bias[col], b1 = bias[col + 1];
                v00 += b0; v01 += b1; v10 += b0; v11 += b1;
            }
            if (EPI == 2) {
                v00 = gelu_exact(v00); v01 = gelu_exact(v01);
                v10 = gelu_exact(v10); v11 = gelu_exact(v11);
            }
            const long long o0 = (long long)row * N + col;
            const long long o1 = (long long)(row + 8) * N + col;
            if (EPI == 2 || EPI == 3) {
                *(uint32_t*)(Ch + o0) = pack2(v00, v01);
                *(uint32_t*)(Ch + o1) = pack2(v10, v11);
            } else {
                *(float2*)(Cf + o0) = make_float2(v00, v01);
                *(float2*)(Cf + o1) = make_float2(v10, v11);
            }
        }
    }
}

// ============ weight prep: transpose [K,N] f32 -> [N,K] fp16 ============
__global__ __launch_bounds__(256)
void wprep(const float* __restrict__ W, __half* __restrict__ Tt, int K, int N)
{
    __shared__ float t[32][33];
    const int n0 = blockIdx.x * 32, k0 = blockIdx.y * 32;
    const int tx = threadIdx.x & 31, ty = threadIdx.x >> 5;   // ty: 0..7
    #pragma unroll
    for (int i = 0; i < 4; i++)
        t[ty + i * 8][tx] = W[(long long)(k0 + ty + i * 8) * N + n0 + tx];
    __syncthreads();
    #pragma unroll
    for (int i = 0; i < 4; i++) {
        const int n = ty + i * 8;
        Tt[(long long)(n0 + n) * K + k0 + tx] = __float2half_rn(t[tx][n]);
    }
}

// ================= fp16 tensor-core flash attention =================
// grid (T/128, H, B), 256 threads = 8 warps; warp w owns 16 query rows.
// C-frag of QK^T maps directly to A-frag of PV (no smem staging for P).
__global__ __launch_bounds__(256)
void attn_f16(const __half* __restrict__ kqv, __half* __restrict__ res)
{
    __shared__ __half Ks [64][72];   // [key][dim]
    __shared__ __half Vst[64][72];   // [dim][key]  (transposed)

    const int tid  = threadIdx.x;
    const int w    = tid >> 5;
    const int lane = tid & 31;
    const int g    = lane >> 2;
    const int t4   = lane & 3;
    const int b    = blockIdx.z;
    const int h    = blockIdx.y;
    const int q0   = blockIdx.x * 128 + w * 16;

    const long long rowstride = (long long)HH * 192;
    const __half* base = kqv + ((long long)b * TT * HH + h) * 192;

    // Q A-frags: rows (q0+g, q0+8+g), k-tiles of 16 dims
    uint32_t qf[4][4];
    {
        const __half* qp0 = base + (long long)(q0 + g)     * rowstride + 64;
        const __half* qp1 = base + (long long)(q0 + 8 + g) * rowstride + 64;
        #pragma unroll
        for (int kk = 0; kk < 4; kk++) {
            qf[kk][0] = *(const uint32_t*)(qp0 + kk * 16 + 2 * t4);
            qf[kk][1] = *(const uint32_t*)(qp1 + kk * 16 + 2 * t4);
            qf[kk][2] = *(const uint32_t*)(qp0 + kk * 16 + 2 * t4 + 8);
            qf[kk][3] = *(const uint32_t*)(qp1 + kk * 16 + 2 * t4 + 8);
        }
    }

    float acc[8][4];
    #pragma unroll
    for (int nt = 0; nt < 8; nt++)
        #pragma unroll
        for (int i = 0; i < 4; i++) acc[nt][i] = 0.f;
    float m0v = -1e30f, m1v = -1e30f, l0 = 0.f, l1 = 0.f;

    for (int j0 = 0; j0 < TT; j0 += 64) {
        // cooperative K/V tile load; V stored transposed
        #pragma unroll
        for (int i = 0; i < 2; i++) {
            int fi = tid + i * 256;          // 0..511
            int r = fi >> 3, c = (fi & 7) * 8;
            const __half* kp = base + (long long)(j0 + r) * rowstride;
            uint4 kv = *(const uint4*)(kp + c);
            *(uint2*)&Ks[r][c]     = make_uint2(kv.x, kv.y);
            *(uint2*)&Ks[r][c + 4] = make_uint2(kv.z, kv.w);
            uint4 vv = *(const uint4*)(kp + 128 + c);
            const __half* vh = (const __half*)&vv;
            #pragma unroll
            for (int d = 0; d < 8; d++) Vst[c + d][r] = vh[d];
        }
        __syncthreads();

        // S = Q @ K^T
        float s[8][4];
        #pragma unroll
        for (int nt = 0; nt < 8; nt++) {
            s[nt][0] = s[nt][1] = s[nt][2] = s[nt][3] = 0.f;
            #pragma unroll
            for (int kk = 0; kk < 4; kk++) {
                uint32_t bb[2];
                bb[0] = *(uint32_t*)&Ks[nt * 8 + g][kk * 16 + 2 * t4];
                bb[1] = *(uint32_t*)&Ks[nt * 8 + g][kk * 16 + 2 * t4 + 8];
                mma_f16(s[nt], qf[kk], bb, s[nt]);
            }
        }

        // online softmax (rows g / g+8; quad reduction)
        float rmax0 = -1e30f, rmax1 = -1e30f;
        #pragma unroll
        for (int nt = 0; nt < 8; nt++) {
            s[nt][0] *= 0.125f; s[nt][1] *= 0.125f;
            s[nt][2] *= 0.125f; s[nt][3] *= 0.125f;
            rmax0 = fmaxf(rmax0, fmaxf(s[nt][0], s[nt][1]));
            rmax1 = fmaxf(rmax1, fmaxf(s[nt][2], s[nt][3]));
        }
        rmax0 = fmaxf(rmax0, __shfl_xor_sync(0xffffffffu, rmax0, 1));
        rmax0 = fmaxf(rmax0, __shfl_xor_sync(0xffffffffu, rmax0, 2));
        rmax1 = fmaxf(rmax1, __shfl_xor_sync(0xffffffffu, rmax1, 1));
        rmax1 = fmaxf(rmax1, __shfl_xor_sync(0xffffffffu, rmax1, 2));

        float mn0 = fmaxf(m0v, rmax0), mn1 = fmaxf(m1v, rmax1);
        float c0 = __expf(m0v - mn0), c1 = __expf(m1v - mn1);
        m0v = mn0; m1v = mn1;

        float ps0 = 0.f, ps1 = 0.f;
        #pragma unroll
        for (int nt = 0; nt < 8; nt++) {
            s[nt][0] = __expf(s[nt][0] - mn0); ps0 += s[nt][0];
            s[nt][1] = __expf(s[nt][1] - mn0); ps0 += s[nt][1];
            s[nt][2] = __expf(s[nt][2] - mn1); ps1 += s[nt][2];
            s[nt][3] = __expf(s[nt][3] - mn1); ps1 += s[nt][3];
        }
        ps0 += __shfl_xor_sync(0xffffffffu, ps0, 1);
        ps0 += __shfl_xor_sync(0xffffffffu, ps0, 2);
        ps1 += __shfl_xor_sync(0xffffffffu, ps1, 1);
        ps1 += __shfl_xor_sync(0xffffffffu, ps1, 2);
        l0 = l0 * c0 + ps0;
        l1 = l1 * c1 + ps1;

        #pragma unroll
        for (int nt = 0; nt < 8; nt++) {
            acc[nt][0] *= c0; acc[nt][1] *= c0;
            acc[nt][2] *= c1; acc[nt][3] *= c1;
        }

        // P C-frag -> A-frag directly (keys = k dim of PV mma)
        uint32_t af[4][4];
        #pragma unroll
        for (int kk = 0; kk < 4; kk++) {
            af[kk][0] = pack2(s[2 * kk][0],     s[2 * kk][1]);
            af[kk][1] = pack2(s[2 * kk][2],     s[2 * kk][3]);
            af[kk][2] = pack2(s[2 * kk + 1][0], s[2 * kk + 1][1]);
            af[kk][3] = pack2(s[2 * kk + 1][2], s[2 * kk + 1][3]);
        }

        // acc += P @ V  (B-frag from transposed V: contiguous half2 over keys)
        #pragma unroll
        for (int nt = 0; nt < 8; nt++) {
            #pragma unroll
            for (int kk = 0; kk < 4; kk++) {
                uint32_t bb[2];
                bb[0] = *(uint32_t*)&Vst[nt * 8 + g][kk * 16 + 2 * t4];
                bb[1] = *(uint32_t*)&Vst[nt * 8 + g][kk * 16 + 2 * t4 + 8];
                mma_f16(acc[nt], af[kk], bb, acc[nt]);
            }
        }
        __syncthreads();
    }

    const float inv0 = 1.f / l0, inv1 = 1.f / l1;
    const long long o0 = (long long)(b * TT + q0 + g) * EMB + h * SS;
    const long long o1 = (long long)(b * TT + q0 + 8 + g) * EMB + h * SS;
    #pragma unroll
    for (int nt = 0; nt < 8; nt++) {
        *(uint32_t*)(res + o0 + nt * 8 + 2 * t4) = pack2(acc[nt][0] * inv0, acc[nt][1] * inv0);
        *(uint32_t*)(res + o1 + nt * 8 + 2 * t4) = pack2(acc[nt][2] * inv1, acc[nt][3] * inv1);
    }
}

// ---------------- fused residual + LayerNorm (+optional fp16 copy) ------
__global__ __launch_bounds__(256)
void ln_kernel(const float* __restrict__ X, const float* __restrict__ Y,
               const float* __restrict__ g, const float* __restrict__ bta,
               float* __restrict__ out, __half* __restrict__ oh)
{
    const int row = blockIdx.x;
    const int tid = threadIdx.x;
    const float* xr = X + (long long)row * EMB;
    const float* yr = Y + (long long)row * EMB;

    float v[4], s = 0.f, ss = 0.f;
    #pragma unroll
    for (int i = 0; i < 4; i++) {
        int c = tid + i * 256;
        float t = xr[c] + yr[c];
        v[i] = t;
        s += t;
        ss = fmaf(t, t, ss);
    }

    __shared__ float rs[8], rss[8];
    #pragma unroll
    for (int o = 16; o > 0; o >>= 1) {
        s  += __shfl_xor_sync(0xffffffffu, s,  o);
        ss += __shfl_xor_sync(0xffffffffu, ss, o);
    }
    const int warp = tid >> 5, lane = tid & 31;
    if (lane == 0) { rs[warp] = s; rss[warp] = ss; }
    __syncthreads();
    float ts = 0.f, tss = 0.f;
    #pragma unroll
    for (int i = 0; i < 8; i++) { ts += rs[i]; tss += rss[i]; }

    const float mean = ts * (1.0f / EMB);
    const float var  = tss * (1.0f / EMB) - mean * mean;
    const float rstd = rsqrtf(var + 1e-5f);

    #pragma unroll
    for (int i = 0; i < 4; i++) {
        int c = tid + i * 256;
        float o = (v[i] - mean) * rstd * g[c] + bta[c];
        if (out) out[(long long)row * EMB + c] = o;
        if (oh)  oh [(long long)row * EMB + c] = __float2half_rn(o);
    }
}

// ---------------- launch --------------------------------------------------
extern "C" void kernel_launch(void* const* d_in, const int* in_sizes, int n_in,
                              void* d_out, int out_size)
{
    const float* x     = (const float*)d_in[0];
    const float* Wkqv  = (const float*)d_in[1];
    const float* Wproj = (const float*)d_in[2];
    const float* g1    = (const float*)d_in[3];
    const float* b1    = (const float*)d_in[4];
    const float* W1    = (const float*)d_in[5];
    const float* bff1  = (const float*)d_in[6];
    const float* W2    = (const float*)d_in[7];
    const float* bff2  = (const float*)d_in[8];
    const float* g2    = (const float*)d_in[9];
    const float* b2    = (const float*)d_in[10];
    float* out = (float*)d_out;

    float *p_mha, *p_x1, *p_ff;
    __half *p_kqv, *p_res, *p_x1h, *p_hh, *p_Wkt, *p_Wpt, *p_W1t, *p_W2t;
    cudaGetSymbolAddress((void**)&p_kqv, g_kqv);
    cudaGetSymbolAddress((void**)&p_res, g_res);
    cudaGetSymbolAddress((void**)&p_mha, g_mha);
    cudaGetSymbolAddress((void**)&p_x1,  g_x1);
    cudaGetSymbolAddress((void**)&p_x1h, g_x1h);
    cudaGetSymbolAddress((void**)&p_hh,  g_hh);
    cudaGetSymbolAddress((void**)&p_ff,  g_ff);
    cudaGetSymbolAddress((void**)&p_Wkt, g_Wkt);
    cudaGetSymbolAddress((void**)&p_Wpt, g_Wpt);
    cudaGetSymbolAddress((void**)&p_W1t, g_W1t);
    cudaGetSymbolAddress((void**)&p_W2t, g_W2t);

    // 0) weight prep: transpose + fp16
    wprep<<<dim3(192 / 32, SS / 32), 256>>>(Wkqv, p_Wkt, SS, 192);
    wprep<<<dim3(EMB / 32, EMB / 32), 256>>>(Wproj, p_Wpt, EMB, EMB);
    wprep<<<dim3(FF4 / 32, EMB / 32), 256>>>(W1, p_W1t, EMB, FF4);
    wprep<<<dim3(EMB / 32, FF4 / 32), 256>>>(W2, p_W2t, FF4, EMB);

    // 1) kqv = xh @ Wkqv : [65536,64] @ [64,192] -> fp16
    gemm_f16<64, 3, true><<<dim3(192 / 64, (ROWS * HH) / 128), 256>>>(
        x, nullptr, p_Wkt, nullptr, nullptr, p_kqv, ROWS * HH, 192, SS);
    // 2) attention -> res (fp16)
    attn_f16<<<dim3(TT / 128, HH, BB), 256>>>(p_kqv, p_res);
    // 3) mha = res @ Wproj
    gemm_f16<128, 0, false><<<dim3(EMB / 128, ROWS / 128), 256>>>(
        nullptr, p_res, p_Wpt, nullptr, p_mha, nullptr, ROWS, EMB, EMB);
    // 4) x1 = LN(x + mha)  (+ fp16 copy)
    ln_kernel<<<ROWS, 256>>>(x, p_mha, g1, b1, p_x1, p_x1h);
    // 5) h = gelu(x1 @ W1 + bff1) -> fp16
    gemm_f16<128, 2, false><<<dim3(FF4 / 128, ROWS / 128), 256>>>(
        nullptr, p_x1h, p_W1t, bff1, nullptr, p_hh, ROWS, FF4, EMB);
    // 6) ff = h @ W2 + bff2
    gemm_f16<128, 1, false><<<dim3(EMB / 128, ROWS / 128), 256>>>(
        nullptr, p_hh, p_W2t, bff2, p_ff, nullptr, ROWS, EMB, FF4);
    // 7) out = LN(x1 + ff)
    ln_kernel<<<ROWS, 256>>>(p_x1, p_ff, g2, b2, out, nullptr);
}

// round 11
// speedup vs baseline: 7.9643x; 1.3040x over previous
#include <cuda_runtime.h>
#include <cuda_fp16.h>
#include <math.h>
#include <stdint.h>

// ---------------- problem constants ----------------
#define BB   2
#define TT   2048
#define HH   16
#define SS   64
#define EMB  1024          // HH*SS
#define ROWS (BB*TT)       // 4096
#define FF4  (4*EMB)       // 4096

// ---------------- scratch (device globals; no allocation) ----------------
__device__ __half g_xh [(long long)ROWS * EMB];      // x in fp16
__device__ __half g_kqv[(long long)ROWS * HH * 192]; // [B,T,H,192] (k|q|v) fp16
__device__ __half g_res[(long long)ROWS * EMB];      // attention out (fp16)
__device__ float  g_mha[(long long)ROWS * EMB];
__device__ float  g_x1 [(long long)ROWS * EMB];
__device__ __half g_x1h[(long long)ROWS * EMB];
__device__ __half g_hh [(long long)ROWS * FF4];
__device__ float  g_ff [(long long)ROWS * EMB];
// transposed fp16 weights: [N, K]
__device__ __half g_Wkt[(long long)192 * SS];
__device__ __half g_Wpt[(long long)EMB * EMB];
__device__ __half g_W1t[(long long)FF4 * EMB];
__device__ __half g_W2t[(long long)EMB * FF4];

// ---------------- helpers ----------------
__device__ __forceinline__ float gelu_exact(float v) {
    return 0.5f * v * (1.0f + erff(v * 0.70710678118654752440f));
}
__device__ __forceinline__ void mma_f16(float (&d)[4], const uint32_t (&a)[4],
                                        const uint32_t b0, const uint32_t b1,
                                        const float (&c)[4]) {
    asm volatile(
        "mma.sync.aligned.m16n8k16.row.col.f32.f16.f16.f32 "
        "{%0,%1,%2,%3}, {%4,%5,%6,%7}, {%8,%9}, {%10,%11,%12,%13};\n"
        : "=f"(d[0]), "=f"(d[1]), "=f"(d[2]), "=f"(d[3])
        : "r"(a[0]), "r"(a[1]), "r"(a[2]), "r"(a[3]),
          "r"(b0), "r"(b1),
          "f"(c[0]), "f"(c[1]), "f"(c[2]), "f"(c[3]));
}
__device__ __forceinline__ uint32_t pack2(float lo, float hi) {
    __half2 h = __floats2half2_rn(lo, hi);
    return *(uint32_t*)&h;
}
__device__ __forceinline__ uint32_t smem_u32(const void* p) {
    uint32_t a;
    asm("{ .reg .u64 t; cvta.to.shared.u64 t, %1; cvt.u32.u64 %0, t; }" : "=r"(a) : "l"(p));
    return a;
}
__device__ __forceinline__ void cp16(uint32_t dst, const void* src) {
    asm volatile("cp.async.cg.shared.global [%0], [%1], 16;" :: "r"(dst), "l"(src));
}
__device__ __forceinline__ void cp_commit() {
    asm volatile("cp.async.commit_group;" ::: "memory");
}
template<int N>
__device__ __forceinline__ void cp_wait() {
    asm volatile("cp.async.wait_group %0;" :: "n"(N) : "memory");
}
__device__ __forceinline__ void ldm_x4(uint32_t& r0, uint32_t& r1, uint32_t& r2,
                                       uint32_t& r3, uint32_t addr) {
    asm volatile("ldmatrix.sync.aligned.m8n8.x4.shared.b16 {%0,%1,%2,%3}, [%4];"
                 : "=r"(r0), "=r"(r1), "=r"(r2), "=r"(r3) : "r"(addr));
}
__device__ __forceinline__ void ldm_x4_t(uint32_t& r0, uint32_t& r1, uint32_t& r2,
                                         uint32_t& r3, uint32_t addr) {
    asm volatile("ldmatrix.sync.aligned.m8n8.x4.trans.shared.b16 {%0,%1,%2,%3}, [%4];"
                 : "=r"(r0), "=r"(r1), "=r"(r2), "=r"(r3) : "r"(addr));
}

// ================= fp16 GEMM: 3-stage cp.async + ldmatrix =================
// C[M,N] = A[M,K] @ Bt[N,K]^T.  BM=128, BK=32, BN in {64,128}.
// 256 threads = 8 warps (4m x 2n); warp tile 32 x (BN/2).
// EPI: 0 = f32; 1 = +bias f32; 2 = +bias+gelu f16; 3 = plain f16.
template<int BN, int EPI>
__global__ __launch_bounds__(256)
void gemm_f16(const __half* __restrict__ Ah, const __half* __restrict__ Bt,
              const float* __restrict__ bias,
              float* __restrict__ Cf, __half* __restrict__ Ch,
              int M, int N, int K)
{
    constexpr int BM = 128, BK = 32;
    constexpr int WN  = BN / 2;
    constexpr int NT  = WN / 8;             // n8 tiles per warp (4 or 8)
    constexpr int NP  = NT / 2;             // nt pairs
    constexpr int LDP = 40;                 // padded row stride (halves)
    constexpr int ABYTES = BM * LDP * 2;    // 10240
    constexpr int BBYTES = BN * LDP * 2;
    constexpr int STB = ABYTES + BBYTES;

    extern __shared__ char smc[];
    const uint32_t sbase = smem_u32(smc);

    const int tid  = threadIdx.x;
    const int w    = tid >> 5;
    const int lane = tid & 31;
    const int g    = lane >> 2;
    const int t4   = lane & 3;
    const int wm   = w >> 1;
    const int wn   = w & 1;
    const int m0   = blockIdx.y * BM;
    const int n0   = blockIdx.x * BN;

    float acc[2][NT][4];
    #pragma unroll
    for (int mt = 0; mt < 2; mt++)
        #pragma unroll
        for (int nt = 0; nt < NT; nt++)
            #pragma unroll
            for (int i = 0; i < 4; i++) acc[mt][nt][i] = 0.f;

    const int nk = K >> 5;      // BK=32 slabs

    // cp.async slab loader (A: 512 chunks, B: BN*4 chunks, 16B each)
    const int ar = tid >> 2, ach = tid & 3;
    auto load_slab = [&](int kt, int st) {
        const uint32_t sa = sbase + (uint32_t)st * STB;
        #pragma unroll
        for (int i = 0; i < 2; i++) {
            int r = ar + i * 64;
            cp16(sa + (uint32_t)(r * LDP + ach * 8) * 2,
                 Ah + (long long)(m0 + r) * K + kt * 32 + ach * 8);
        }
        const uint32_t sb = sa + ABYTES;
        #pragma unroll
        for (int i = 0; i < BN / 64; i++) {
            int r = ar + i * 64;
            cp16(sb + (uint32_t)(r * LDP + ach * 8) * 2,
                 Bt + (long long)(n0 + r) * K + kt * 32 + ach * 8);
        }
        cp_commit();
    };

    // per-lane ldmatrix base offsets (bytes)
    const uint32_t aoff = (uint32_t)((wm * 32 + (lane & 15)) * LDP + (lane >> 4) * 8) * 2;
    const uint32_t boff = (uint32_t)((wn * WN + (lane >> 4) * 8 + (lane & 7)) * LDP
                                     + ((lane >> 3) & 1) * 8) * 2;

    // prologue: stage 0,1
    load_slab(0, 0);
    if (nk > 1) load_slab(1, 1);

    for (int kt = 0; kt < nk; ++kt) {
        const int st = kt % 3;
        if (kt + 1 < nk) cp_wait<1>(); else cp_wait<0>();
        __syncthreads();
        if (kt + 2 < nk) load_slab(kt + 2, (kt + 2) % 3);

        const uint32_t sa = sbase + (uint32_t)st * STB;
        const uint32_t sb = sa + ABYTES;
        #pragma unroll
        for (int ks = 0; ks < 2; ks++) {
            uint32_t a[2][4];
            #pragma unroll
            for (int mt = 0; mt < 2; mt++)
                ldm_x4(a[mt][0], a[mt][1], a[mt][2], a[mt][3],
                       sa + aoff + (uint32_t)mt * (16 * LDP * 2) + ks * 32);
            #pragma unroll
            for (int np = 0; np < NP; np++) {
                uint32_t r0, r1, r2, r3;
                ldm_x4(r0, r1, r2, r3,
                       sb + boff + (uint32_t)np * (16 * LDP * 2) + ks * 32);
                mma_f16(acc[0][2 * np],     a[0], r0, r1, acc[0][2 * np]);
                mma_f16(acc[1][2 * np],     a[1], r0, r1, acc[1][2 * np]);
                mma_f16(acc[0][2 * np + 1], a[0], r2, r3, acc[0][2 * np + 1]);
                mma_f16(acc[1][2 * np + 1], a[1], r2, r3, acc[1][2 * np + 1]);
            }
        }
        __syncthreads();
    }

    // epilogue
    #pragma unroll
    for (int mt = 0; mt < 2; mt++) {
        int row = m0 + wm * 32 + mt * 16 + g;
        #pragma unroll
        for (int nt = 0; nt < NT; nt++) {
            int col = n0 + wn * WN + nt * 8 + 2 * t4;
            float v00 = acc[mt][nt][0], v01 = acc[mt][nt][1];
            float v10 = acc[mt][nt][2], v11 = acc[mt][nt][3];
            if (EPI == 1 || EPI == 2) {
                float b0 = bias[col], b1 = bias[col + 1];
                v00 += b0; v01 += b1; v10 += b0; v11 += b1;
            }
            if (EPI == 2) {
                v00 = gelu_exact(v00); v01 = gelu_exact(v01);
                v10 = gelu_exact(v10); v11 = gelu_exact(v11);
            }
            const long long o0 = (long long)row * N + col;
            const long long o1 = (long long)(row + 8) * N + col;
            if (EPI == 2 || EPI == 3) {
                *(uint32_t*)(Ch + o0) = pack2(v00, v01);
                *(uint32_t*)(Ch + o1) = pack2(v10, v11);
            } else {
                *(float2*)(Cf + o0) = make_float2(v00, v01);
                *(float2*)(Cf + o1) = make_float2(v10, v11);
            }
        }
    }
}

// ============ weight prep: transpose [K,N] f32 -> [N,K] fp16 ============
__global__ __launch_bounds__(256)
void wprep(const float* __restrict__ W, __half* __restrict__ Tt, int K, int N)
{
    __shared__ float t[32][33];
    const int n0 = blockIdx.x * 32, k0 = blockIdx.y * 32;
    const int tx = threadIdx.x & 31, ty = threadIdx.x >> 5;
    #pragma unroll
    for (int i = 0; i < 4; i++)
        t[ty + i * 8][tx] = W[(long long)(k0 + ty + i * 8) * N + n0 + tx];
    __syncthreads();
    #pragma unroll
    for (int i = 0; i < 4; i++) {
        const int n = ty + i * 8;
        Tt[(long long)(n0 + n) * K + k0 + tx] = __float2half_rn(t[tx][n]);
    }
}

// ============ x convert: f32 -> fp16 ============
__global__ __launch_bounds__(256)
void xcvt(const float* __restrict__ X, __half* __restrict__ Xh)
{
    const long long i = ((long long)blockIdx.x * 256 + threadIdx.x) * 4;
    float4 v = *(const float4*)(X + i);
    __half h[4] = {__float2half_rn(v.x), __float2half_rn(v.y),
                   __float2half_rn(v.z), __float2half_rn(v.w)};
    *(uint2*)(Xh + i) = *(uint2*)h;
}

// ================= fp16 flash attention: cp.async + ldmatrix =================
// grid (T/128, H, B), 256 threads = 8 warps; warp w owns 16 query rows.
__global__ __launch_bounds__(256)
void attn_f16(const __half* __restrict__ kqv, __half* __restrict__ res)
{
    __shared__ __half Ks[2][64][72];   // [key][dim]
    __shared__ __half Vs[2][64][72];   // [key][dim] raw; transposed via ldmatrix.trans

    const int tid  = threadIdx.x;
    const int w    = tid >> 5;
    const int lane = tid & 31;
    const int g    = lane >> 2;
    const int t4   = lane & 3;
    const int b    = blockIdx.z;
    const int h    = blockIdx.y;
    const int q0   = blockIdx.x * 128 + w * 16;

    const long long rowstride = (long long)HH * 192;
    const __half* base = kqv + ((long long)b * TT * HH + h) * 192;

    // Q A-frags, pre-scaled by 1/sqrt(S) = 0.125 (exact in fp16)
    uint32_t qf[4][4];
    {
        const __half2 sc = __float2half2_rn(0.125f);
        const __half* qp0 = base + (long long)(q0 + g)     * rowstride + 64;
        const __half* qp1 = base + (long long)(q0 + 8 + g) * rowstride + 64;
        #pragma unroll
        for (int kk = 0; kk < 4; kk++) {
            __half2 v0 = __hmul2(*(const __half2*)(qp0 + kk * 16 + 2 * t4), sc);
            __half2 v1 = __hmul2(*(const __half2*)(qp1 + kk * 16 + 2 * t4), sc);
            __half2 v2 = __hmul2(*(const __half2*)(qp0 + kk * 16 + 2 * t4 + 8), sc);
            __half2 v3 = __hmul2(*(const __half2*)(qp1 + kk * 16 + 2 * t4 + 8), sc);
            qf[kk][0] = *(uint32_t*)&v0; qf[kk][1] = *(uint32_t*)&v1;
            qf[kk][2] = *(uint32_t*)&v2; qf[kk][3] = *(uint32_t*)&v3;
        }
    }

    const uint32_t ks_base = smem_u32(&Ks[0][0][0]);
    const uint32_t vs_base = smem_u32(&Vs[0][0][0]);
    constexpr uint32_t STAGE = 64 * 72 * 2;   // 9216 B

    // per-lane ldmatrix offsets (bytes)
    const uint32_t klane = (uint32_t)(((lane >> 4) * 8 + (lane & 7)) * 144
                                      + ((lane >> 3) & 1) * 16);
    const uint32_t vlane = (uint32_t)((lane & 15) * 144 + (lane >> 4) * 16);

    // cp.async tile loader: K + V, one group
    const int lr = tid >> 3, lch = (tid & 7) * 8;
    auto load_tile = [&](int j0, int buf) {
        #pragma unroll
        for (int j = 0; j < 2; j++) {
            const int r = lr + j * 32;
            const __half* kp = base + (long long)(j0 + r) * rowstride;
            cp16(ks_base + buf * STAGE + (uint32_t)(r * 144 + lch * 2), kp + lch);
            cp16(vs_base + buf * STAGE + (uint32_t)(r * 144 + lch * 2), kp + 128 + lch);
        }
        cp_commit();
    };

    float acc[8][4];
    #pragma unroll
    for (int nt = 0; nt < 8; nt++)
        #pragma unroll
        for (int i = 0; i < 4; i++) acc[nt][i] = 0.f;
    float m0v = -1e30f, m1v = -1e30f, l0 = 0.f, l1 = 0.f;

    load_tile(0, 0);

    for (int it = 0; it < TT / 64; ++it) {
        const int buf = it & 1;
        cp_wait<0>();
        __syncthreads();
        if (it + 1 < TT / 64) load_tile((it + 1) * 64, buf ^ 1);

        const uint32_t kb = ks_base + buf * STAGE + klane;
        const uint32_t vb = vs_base + buf * STAGE + vlane;

        // S = (Q/8) @ K^T
        float s[8][4];
        #pragma unroll
        for (int np = 0; np < 4; np++) {
            s[2*np][0] = s[2*np][1] = s[2*np][2] = s[2*np][3] = 0.f;
            s[2*np+1][0] = s[2*np+1][1] = s[2*np+1][2] = s[2*np+1][3] = 0.f;
            #pragma unroll
            for (int kk = 0; kk < 4; kk++) {
                uint32_t r0, r1, r2, r3;
                ldm_x4(r0, r1, r2, r3, kb + (uint32_t)(np * 16 * 144 + kk * 32));
                mma_f16(s[2*np],     qf[kk], r0, r1, s[2*np]);
                mma_f16(s[2*np+1],   qf[kk], r2, r3, s[2*np+1]);
            }
        }

        // online softmax (rows g / g+8; quad reduction)
        float rmax0 = -1e30f, rmax1 = -1e30f;
        #pragma unroll
        for (int nt = 0; nt < 8; nt++) {
            rmax0 = fmaxf(rmax0, fmaxf(s[nt][0], s[nt][1]));
            rmax1 = fmaxf(rmax1, fmaxf(s[nt][2], s[nt][3]));
        }
        rmax0 = fmaxf(rmax0, __shfl_xor_sync(0xffffffffu, rmax0, 1));
        rmax0 = fmaxf(rmax0, __shfl_xor_sync(0xffffffffu, rmax0, 2));
        rmax1 = fmaxf(rmax1, __shfl_xor_sync(0xffffffffu, rmax1, 1));
        rmax1 = fmaxf(rmax1, __shfl_xor_sync(0xffffffffu, rmax1, 2));

        float mn0 = fmaxf(m0v, rmax0), mn1 = fmaxf(m1v, rmax1);
        float c0 = __expf(m0v - mn0), c1 = __expf(m1v - mn1);
        m0v = mn0; m1v = mn1;

        float ps0 = 0.f, ps1 = 0.f;
        #pragma unroll
        for (int nt = 0; nt < 8; nt++) {
            s[nt][0] = __expf(s[nt][0] - mn0); ps0 += s[nt][0];
            s[nt][1] = __expf(s[nt][1] - mn0); ps0 += s[nt][1];
            s[nt][2] = __expf(s[nt][2] - mn1); ps1 += s[nt][2];
            s[nt][3] = __expf(s[nt][3] - mn1); ps1 += s[nt][3];
        }
        ps0 += __shfl_xor_sync(0xffffffffu, ps0, 1);
        ps0 += __shfl_xor_sync(0xffffffffu, ps0, 2);
        ps1 += __shfl_xor_sync(0xffffffffu, ps1, 1);
        ps1 += __shfl_xor_sync(0xffffffffu, ps1, 2);
        l0 = l0 * c0 + ps0;
        l1 = l1 * c1 + ps1;

        #pragma unroll
        for (int nt = 0; nt < 8; nt++) {
            acc[nt][0] *= c0; acc[nt][1] *= c0;
            acc[nt][2] *= c1; acc[nt][3] *= c1;
        }

        // P C-frag -> A-frag directly (keys become k of PV mma)
        uint32_t af[4][4];
        #pragma unroll
        for (int kk = 0; kk < 4; kk++) {
            af[kk][0] = pack2(s[2 * kk][0],     s[2 * kk][1]);
            af[kk][1] = pack2(s[2 * kk][2],     s[2 * kk][3]);
            af[kk][2] = pack2(s[2 * kk + 1][0], s[2 * kk + 1][1]);
            af[kk][3] = pack2(s[2 * kk + 1][2], s[2 * kk + 1][3]);
        }

        // acc += P @ V  (B-frags via ldmatrix.trans on raw V)
        #pragma unroll
        for (int np = 0; np < 4; np++) {
            #pragma unroll
            for (int kk = 0; kk < 4; kk++) {
                uint32_t r0, r1, r2, r3;
                ldm_x4_t(r0, r1, r2, r3, vb + (uint32_t)(kk * 16 * 144 + np * 32));
                mma_f16(acc[2*np],   af[kk], r0, r1, acc[2*np]);
                mma_f16(acc[2*np+1], af[kk], r2, r3, acc[2*np+1]);
            }
        }
        __syncthreads();
    }

    const float inv0 = 1.f / l0, inv1 = 1.f / l1;
    const long long o0 = (long long)(b * TT + q0 + g) * EMB + h * SS;
    const long long o1 = (long long)(b * TT + q0 + 8 + g) * EMB + h * SS;
    #pragma unroll
    for (int nt = 0; nt < 8; nt++) {
        *(uint32_t*)(res + o0 + nt * 8 + 2 * t4) = pack2(acc[nt][0] * inv0, acc[nt][1] * inv0);
        *(uint32_t*)(res + o1 + nt * 8 + 2 * t4) = pack2(acc[nt][2] * inv1, acc[nt][3] * inv1);
    }
}

// ---------------- fused residual + LayerNorm (+optional fp16 copy) ------
__global__ __launch_bounds__(256)
void ln_kernel(const float* __restrict__ X, const float* __restrict__ Y,
               const float* __restrict__ g, const float* __restrict__ bta,
               float* __restrict__ out, __half* __restrict__ oh)
{
    const int row = blockIdx.x;
    const int tid = threadIdx.x;
    const float* xr = X + (long long)row * EMB;
    const float* yr = Y + (long long)row * EMB;

    float v[4], s = 0.f, ss = 0.f;
    #pragma unroll
    for (int i = 0; i < 4; i++) {
        int c = tid + i * 256;
        float t = xr[c] + yr[c];
        v[i] = t;
        s += t;
        ss = fmaf(t, t, ss);
    }

    __shared__ float rs[8], rss[8];
    #pragma unroll
    for (int o = 16; o > 0; o >>= 1) {
        s  += __shfl_xor_sync(0xffffffffu, s,  o);
        ss += __shfl_xor_sync(0xffffffffu, ss, o);
    }
    const int warp = tid >> 5, lane = tid & 31;
    if (lane == 0) { rs[warp] = s; rss[warp] = ss; }
    __syncthreads();
    float ts = 0.f, tss = 0.f;
    #pragma unroll
    for (int i = 0; i < 8; i++) { ts += rs[i]; tss += rss[i]; }

    const float mean = ts * (1.0f / EMB);
    const float var  = tss * (1.0f / EMB) - mean * mean;
    const float rstd = rsqrtf(var + 1e-5f);

    #pragma unroll
    for (int i = 0; i < 4; i++) {
        int c = tid + i * 256;
        float o = (v[i] - mean) * rstd * g[c] + bta[c];
        if (out) out[(long long)row * EMB + c] = o;
        if (oh)  oh [(long long)row * EMB + c] = __float2half_rn(o);
    }
}

// ---------------- launch --------------------------------------------------
extern "C" void kernel_launch(void* const* d_in, const int* in_sizes, int n_in,
                              void* d_out, int out_size)
{
    const float* x     = (const float*)d_in[0];
    const float* Wkqv  = (const float*)d_in[1];
    const float* Wproj = (const float*)d_in[2];
    const float* g1    = (const float*)d_in[3];
    const float* b1    = (const float*)d_in[4];
    const float* W1    = (const float*)d_in[5];
    const float* bff1  = (const float*)d_in[6];
    const float* W2    = (const float*)d_in[7];
    const float* bff2  = (const float*)d_in[8];
    const float* g2    = (const float*)d_in[9];
    const float* b2    = (const float*)d_in[10];
    float* out = (float*)d_out;

    float *p_mha, *p_x1, *p_ff;
    __half *p_xh, *p_kqv, *p_res, *p_x1h, *p_hh, *p_Wkt, *p_Wpt, *p_W1t, *p_W2t;
    cudaGetSymbolAddress((void**)&p_xh,  g_xh);
    cudaGetSymbolAddress((void**)&p_kqv, g_kqv);
    cudaGetSymbolAddress((void**)&p_res, g_res);
    cudaGetSymbolAddress((void**)&p_mha, g_mha);
    cudaGetSymbolAddress((void**)&p_x1,  g_x1);
    cudaGetSymbolAddress((void**)&p_x1h, g_x1h);
    cudaGetSymbolAddress((void**)&p_hh,  g_hh);
    cudaGetSymbolAddress((void**)&p_ff,  g_ff);
    cudaGetSymbolAddress((void**)&p_Wkt, g_Wkt);
    cudaGetSymbolAddress((void**)&p_Wpt, g_Wpt);
    cudaGetSymbolAddress((void**)&p_W1t, g_W1t);
    cudaGetSymbolAddress((void**)&p_W2t, g_W2t);

    constexpr int SM128 = 3 * (128 * 40 * 2 + 128 * 40 * 2);  // 61440
    constexpr int SM64  = 3 * (128 * 40 * 2 + 64 * 40 * 2);   // 46080
    cudaFuncSetAttribute(gemm_f16<128,0>, cudaFuncAttributeMaxDynamicSharedMemorySize, SM128);
    cudaFuncSetAttribute(gemm_f16<128,1>, cudaFuncAttributeMaxDynamicSharedMemorySize, SM128);
    cudaFuncSetAttribute(gemm_f16<128,2>, cudaFuncAttributeMaxDynamicSharedMemorySize, SM128);
    cudaFuncSetAttribute(gemm_f16<64,3>,  cudaFuncAttributeMaxDynamicSharedMemorySize, SM64);

    // 0) conversions / weight prep
    xcvt<<<ROWS, 256>>>(x, p_xh);
    wprep<<<dim3(192 / 32, SS / 32), 256>>>(Wkqv, p_Wkt, SS, 192);
    wprep<<<dim3(EMB / 32, EMB / 32), 256>>>(Wproj, p_Wpt, EMB, EMB);
    wprep<<<dim3(FF4 / 32, EMB / 32), 256>>>(W1, p_W1t, EMB, FF4);
    wprep<<<dim3(EMB / 32, FF4 / 32), 256>>>(W2, p_W2t, FF4, EMB);

    // 1) kqv = xh @ Wkqv : [65536,64] @ [64,192] -> fp16
    gemm_f16<64, 3><<<dim3(192 / 64, (ROWS * HH) / 128), 256, SM64>>>(
        p_xh, p_Wkt, nullptr, nullptr, p_kqv, ROWS * HH, 192, SS);
    // 2) attention -> res (fp16)
    attn_f16<<<dim3(TT / 128, HH, BB), 256>>>(p_kqv, p_res);
    // 3) mha = res @ Wproj
    gemm_f16<128, 0><<<dim3(EMB / 128, ROWS / 128), 256, SM128>>>(
        p_res, p_Wpt, nullptr, p_mha, nullptr, ROWS, EMB, EMB);
    // 4) x1 = LN(x + mha)  (+ fp16 copy)
    ln_kernel<<<ROWS, 256>>>(x, p_mha, g1, b1, p_x1, p_x1h);
    // 5) h = gelu(x1 @ W1 + bff1) -> fp16
    gemm_f16<128, 2><<<dim3(FF4 / 128, ROWS / 128), 256, SM128>>>(
        p_x1h, p_W1t, bff1, nullptr, p_hh, ROWS, FF4, EMB);
    // 6) ff = h @ W2 + bff2
    gemm_f16<128, 1><<<dim3(EMB / 128, ROWS / 128), 256, SM128>>>(
        p_hh, p_W2t, bff2, p_ff, nullptr, ROWS, EMB, FF4);
    // 7) out = LN(x1 + ff)
    ln_kernel<<<ROWS, 256>>>(p_x1, p_ff, g2, b2, out, nullptr);
}

// round 13
// speedup vs baseline: 8.9167x; 1.1196x over previous
#include <cuda_runtime.h>
#include <cuda_fp16.h>
#include <math.h>
#include <stdint.h>

// ---------------- problem constants ----------------
#define BB   2
#define TT   2048
#define HH   16
#define SS   64
#define EMB  1024          // HH*SS
#define ROWS (BB*TT)       // 4096
#define FF4  (4*EMB)       // 4096

// ---------------- scratch (device globals; no allocation) ----------------
__device__ __half g_xh [(long long)ROWS * EMB];      // x in fp16
__device__ __half g_kqv[(long long)ROWS * HH * 192]; // [B,T,H,192] (k|q|v) fp16
__device__ __half g_res[(long long)ROWS * EMB];      // attention out (fp16)
__device__ float  g_mha[(long long)ROWS * EMB];
__device__ float  g_x1 [(long long)ROWS * EMB];
__device__ __half g_x1h[(long long)ROWS * EMB];
__device__ __half g_hh [(long long)ROWS * FF4];
__device__ float  g_ff [(long long)ROWS * EMB];
// fp16 weights, k-major [K, N] (no transpose needed)
__device__ __half g_Wkh[(long long)SS * 192];
__device__ __half g_Wph[(long long)EMB * EMB];
__device__ __half g_W1h[(long long)EMB * FF4];
__device__ __half g_W2h[(long long)FF4 * EMB];

// ---------------- helpers ----------------
__device__ __forceinline__ float gelu_exact(float v) {
    return 0.5f * v * (1.0f + erff(v * 0.70710678118654752440f));
}
__device__ __forceinline__ void mma_f16(float (&d)[4], const uint32_t (&a)[4],
                                        const uint32_t b0, const uint32_t b1,
                                        const float (&c)[4]) {
    asm volatile(
        "mma.sync.aligned.m16n8k16.row.col.f32.f16.f16.f32 "
        "{%0,%1,%2,%3}, {%4,%5,%6,%7}, {%8,%9}, {%10,%11,%12,%13};\n"
        : "=f"(d[0]), "=f"(d[1]), "=f"(d[2]), "=f"(d[3])
        : "r"(a[0]), "r"(a[1]), "r"(a[2]), "r"(a[3]),
          "r"(b0), "r"(b1),
          "f"(c[0]), "f"(c[1]), "f"(c[2]), "f"(c[3]));
}
__device__ __forceinline__ uint32_t pack2(float lo, float hi) {
    __half2 h = __floats2half2_rn(lo, hi);
    return *(uint32_t*)&h;
}
__device__ __forceinline__ uint32_t smem_u32(const void* p) {
    uint32_t a;
    asm("{ .reg .u64 t; cvta.to.shared.u64 t, %1; cvt.u32.u64 %0, t; }" : "=r"(a) : "l"(p));
    return a;
}
__device__ __forceinline__ void cp16(uint32_t dst, const void* src) {
    asm volatile("cp.async.cg.shared.global [%0], [%1], 16;" :: "r"(dst), "l"(src));
}
__device__ __forceinline__ void cp_commit() {
    asm volatile("cp.async.commit_group;" ::: "memory");
}
template<int N>
__device__ __forceinline__ void cp_wait() {
    asm volatile("cp.async.wait_group %0;" :: "n"(N) : "memory");
}
__device__ __forceinline__ void ldm_x4(uint32_t& r0, uint32_t& r1, uint32_t& r2,
                                       uint32_t& r3, uint32_t addr) {
    asm volatile("ldmatrix.sync.aligned.m8n8.x4.shared.b16 {%0,%1,%2,%3}, [%4];"
                 : "=r"(r0), "=r"(r1), "=r"(r2), "=r"(r3) : "r"(addr));
}
__device__ __forceinline__ void ldm_x4_t(uint32_t& r0, uint32_t& r1, uint32_t& r2,
                                         uint32_t& r3, uint32_t addr) {
    asm volatile("ldmatrix.sync.aligned.m8n8.x4.trans.shared.b16 {%0,%1,%2,%3}, [%4];"
                 : "=r"(r0), "=r"(r1), "=r"(r2), "=r"(r3) : "r"(addr));
}

// ================= fp16 GEMM: 64x64 warp tiles, B k-major =================
// C[M,N] = A[M,K] @ B[K,N].  BM=128, BK=64, BN in {64,128}.
// 128 threads = 4 warps (2m x 2n); warp tile 64 x (BN/2).
// B stored k-major in smem; B-frags via ldmatrix.x4.trans (proven in attn PV).
// EPI: 0 = f32; 1 = +bias f32; 2 = +bias+gelu f16; 3 = plain f16.
template<int BN, int EPI>
__global__ __launch_bounds__(128)
void gemm_f16(const __half* __restrict__ Ah, const __half* __restrict__ Bw,
              const float* __restrict__ bias,
              float* __restrict__ Cf, __half* __restrict__ Ch,
              int M, int N, int K)
{
    constexpr int BM = 128, BK = 64;
    constexpr int WN  = BN / 2;             // warp n-extent (64 or 32)
    constexpr int NT  = WN / 8;             // n8 tiles per warp (8 or 4)
    constexpr int NP  = NT / 2;             // 16-col pairs (4 or 2)
    constexpr int LDA = 72;                 // A row stride (halves)
    constexpr int LDB = BN + 8;             // B row stride (halves)
    constexpr int ABY = BM * LDA * 2;       // 18432
    constexpr int BBY = BK * LDB * 2;
    constexpr int STB = ABY + BBY;
    constexpr int CPR = BN / 8;             // B 16B-chunks per row

    extern __shared__ char smc[];
    const uint32_t sbase = smem_u32(smc);

    const int tid  = threadIdx.x;
    const int w    = tid >> 5;
    const int lane = tid & 31;
    const int g    = lane >> 2;
    const int t4   = lane & 3;
    const int wm   = w >> 1;                // 0..1
    const int wn   = w & 1;                 // 0..1
    const int m0   = blockIdx.y * BM;
    const int n0   = blockIdx.x * BN;

    float acc[4][NT][4];
    #pragma unroll
    for (int mt = 0; mt < 4; mt++)
        #pragma unroll
        for (int nt = 0; nt < NT; nt++)
            #pragma unroll
            for (int i = 0; i < 4; i++) acc[mt][nt][i] = 0.f;

    const int nk = K >> 6;   // BK=64 slabs

    auto load_slab = [&](int kt, int st) {
        const uint32_t sa = sbase + (uint32_t)st * STB;
        #pragma unroll
        for (int i = 0; i < 8; i++) {                 // A: 1024 chunks / 128 thr
            int ci = tid + i * 128;
            int r = ci >> 3, c = (ci & 7) * 8;
            cp16(sa + (uint32_t)(r * LDA + c) * 2,
                 Ah + (long long)(m0 + r) * K + kt * 64 + c);
        }
        const uint32_t sb = sa + ABY;
        #pragma unroll
        for (int i = 0; i < (BK * CPR) / 128; i++) {  // B: k-major rows of W
            int ci = tid + i * 128;
            int r = ci / CPR, c = (ci % CPR) * 8;
            cp16(sb + (uint32_t)(r * LDB + c) * 2,
                 Bw + (long long)(kt * 64 + r) * N + n0 + c);
        }
        cp_commit();
    };

    // per-lane ldmatrix base offsets (bytes)
    const uint32_t aoff = (uint32_t)((wm * 64 + (lane & 15)) * LDA + (lane >> 4) * 8) * 2;
    const uint32_t boff = (uint32_t)((lane & 15) * LDB * 2 + (lane >> 4) * 16 + wn * WN * 2);

    load_slab(0, 0);

    for (int kt = 0; kt < nk; ++kt) {
        cp_wait<0>();
        __syncthreads();
        if (kt + 1 < nk) load_slab(kt + 1, (kt + 1) & 1);

        const uint32_t sa = sbase + (uint32_t)(kt & 1) * STB;
        const uint32_t sb = sa + ABY;
        #pragma unroll
        for (int ks = 0; ks < 4; ks++) {
            uint32_t a[4][4];
            #pragma unroll
            for (int mt = 0; mt < 4; mt++)
                ldm_x4(a[mt][0], a[mt][1], a[mt][2], a[mt][3],
                       sa + aoff + (uint32_t)(mt * (16 * LDA * 2) + ks * 32));
            #pragma unroll
            for (int np = 0; np < NP; np++) {
                uint32_t r0, r1, r2, r3;
                ldm_x4_t(r0, r1, r2, r3,
                         sb + boff + (uint32_t)(ks * (16 * LDB * 2) + np * 32));
                #pragma unroll
                for (int mt = 0; mt < 4; mt++) {
                    mma_f16(acc[mt][2 * np],     a[mt], r0, r1, acc[mt][2 * np]);
                    mma_f16(acc[mt][2 * np + 1], a[mt], r2, r3, acc[mt][2 * np + 1]);
                }
            }
        }
    }

    // epilogue
    #pragma unroll
    for (int mt = 0; mt < 4; mt++) {
        int row = m0 + wm * 64 + mt * 16 + g;
        #pragma unroll
        for (int nt = 0; nt < NT; nt++) {
            int col = n0 + wn * WN + nt * 8 + 2 * t4;
            float v00 = acc[mt][nt][0], v01 = acc[mt][nt][1];
            float v10 = acc[mt][nt][2], v11 = acc[mt][nt][3];
            if (EPI == 1 || EPI == 2) {
                float b0 = bias[col], b1 = bias[col + 1];
                v00 += b0; v01 += b1; v10 += b0; v11 += b1;
            }
            if (EPI == 2) {
                v00 = gelu_exact(v00); v01 = gelu_exact(v01);
                v10 = gelu_exact(v10); v11 = gelu_exact(v11);
            }
            const long long o0 = (long long)row * N + col;
            const long long o1 = (long long)(row + 8) * N + col;
            if (EPI == 2 || EPI == 3) {
                *(uint32_t*)(Ch + o0) = pack2(v00, v01);
                *(uint32_t*)(Ch + o1) = pack2(v10, v11);
            } else {
                *(float2*)(Cf + o0) = make_float2(v00, v01);
                *(float2*)(Cf + o1) = make_float2(v10, v11);
            }
        }
    }
}

// ============ streaming convert f32 -> fp16 (no transpose) ============
__global__ __launch_bounds__(256)
void cvt16(const float* __restrict__ X, __half* __restrict__ Xh)
{
    const long long i = ((long long)blockIdx.x * 256 + threadIdx.x) * 4;
    float4 v = *(const float4*)(X + i);
    __half h[4] = {__float2half_rn(v.x), __float2half_rn(v.y),
                   __float2half_rn(v.z), __float2half_rn(v.w)};
    *(uint2*)(Xh + i) = *(uint2*)h;
}

// ================= fp16 flash attention: cp.async + ldmatrix =================
// grid (T/128, H, B), 256 threads = 8 warps; warp w owns 16 query rows.
__global__ __launch_bounds__(256)
void attn_f16(const __half* __restrict__ kqv, __half* __restrict__ res)
{
    __shared__ __half Ks[2][64][72];   // [key][dim]
    __shared__ __half Vs[2][64][72];   // [key][dim] raw; transposed via ldmatrix.trans

    const int tid  = threadIdx.x;
    const int w    = tid >> 5;
    const int lane = tid & 31;
    const int g    = lane >> 2;
    const int t4   = lane & 3;
    const int b    = blockIdx.z;
    const int h    = blockIdx.y;
    const int q0   = blockIdx.x * 128 + w * 16;

    const long long rowstride = (long long)HH * 192;
    const __half* base = kqv + ((long long)b * TT * HH + h) * 192;

    // Q A-frags, pre-scaled by 1/sqrt(S) = 0.125 (exact in fp16)
    uint32_t qf[4][4];
    {
        const __half2 sc = __float2half2_rn(0.125f);
        const __half* qp0 = base + (long long)(q0 + g)     * rowstride + 64;
        const __half* qp1 = base + (long long)(q0 + 8 + g) * rowstride + 64;
        #pragma unroll
        for (int kk = 0; kk < 4; kk++) {
            __half2 v0 = __hmul2(*(const __half2*)(qp0 + kk * 16 + 2 * t4), sc);
            __half2 v1 = __hmul2(*(const __half2*)(qp1 + kk * 16 + 2 * t4), sc);
            __half2 v2 = __hmul2(*(const __half2*)(qp0 + kk * 16 + 2 * t4 + 8), sc);
            __half2 v3 = __hmul2(*(const __half2*)(qp1 + kk * 16 + 2 * t4 + 8), sc);
            qf[kk][0] = *(uint32_t*)&v0; qf[kk][1] = *(uint32_t*)&v1;
            qf[kk][2] = *(uint32_t*)&v2; qf[kk][3] = *(uint32_t*)&v3;
        }
    }

    const uint32_t ks_base = smem_u32(&Ks[0][0][0]);
    const uint32_t vs_base = smem_u32(&Vs[0][0][0]);
    constexpr uint32_t STAGE = 64 * 72 * 2;   // 9216 B

    // per-lane ldmatrix offsets (bytes)
    const uint32_t klane = (uint32_t)(((lane >> 4) * 8 + (lane & 7)) * 144
                                      + ((lane >> 3) & 1) * 16);
    const uint32_t vlane = (uint32_t)((lane & 15) * 144 + (lane >> 4) * 16);

    // cp.async tile loader: K + V, one group
    const int lr = tid >> 3, lch = (tid & 7) * 8;
    auto load_tile = [&](int j0, int buf) {
        #pragma unroll
        for (int j = 0; j < 2; j++) {
            const int r = lr + j * 32;
            const __half* kp = base + (long long)(j0 + r) * rowstride;
            cp16(ks_base + buf * STAGE + (uint32_t)(r * 144 + lch * 2), kp + lch);
            cp16(vs_base + buf * STAGE + (uint32_t)(r * 144 + lch * 2), kp + 128 + lch);
        }
        cp_commit();
    };

    float acc[8][4];
    #pragma unroll
    for (int nt = 0; nt < 8; nt++)
        #pragma unroll
        for (int i = 0; i < 4; i++) acc[nt][i] = 0.f;
    float m0v = -1e30f, m1v = -1e30f, l0 = 0.f, l1 = 0.f;

    load_tile(0, 0);

    for (int it = 0; it < TT / 64; ++it) {
        const int buf = it & 1;
        cp_wait<0>();
        __syncthreads();
        if (it + 1 < TT / 64) load_tile((it + 1) * 64, buf ^ 1);

        const uint32_t kb = ks_base + buf * STAGE + klane;
        const uint32_t vb = vs_base + buf * STAGE + vlane;

        // S = (Q/8) @ K^T
        float s[8][4];
        #pragma unroll
        for (int np = 0; np < 4; np++) {
            s[2*np][0] = s[2*np][1] = s[2*np][2] = s[2*np][3] = 0.f;
            s[2*np+1][0] = s[2*np+1][1] = s[2*np+1][2] = s[2*np+1][3] = 0.f;
            #pragma unroll
            for (int kk = 0; kk < 4; kk++) {
                uint32_t r0, r1, r2, r3;
                ldm_x4(r0, r1, r2, r3, kb + (uint32_t)(np * 16 * 144 + kk * 32));
                mma_f16(s[2*np],     qf[kk], r0, r1, s[2*np]);
                mma_f16(s[2*np+1],   qf[kk], r2, r3, s[2*np+1]);
            }
        }

        // online softmax (rows g / g+8; quad reduction)
        float rmax0 = -1e30f, rmax1 = -1e30f;
        #pragma unroll
        for (int nt = 0; nt < 8; nt++) {
            rmax0 = fmaxf(rmax0, fmaxf(s[nt][0], s[nt][1]));
            rmax1 = fmaxf(rmax1, fmaxf(s[nt][2], s[nt][3]));
        }
        rmax0 = fmaxf(rmax0, __shfl_xor_sync(0xffffffffu, rmax0, 1));
        rmax0 = fmaxf(rmax0, __shfl_xor_sync(0xffffffffu, rmax0, 2));
        rmax1 = fmaxf(rmax1, __shfl_xor_sync(0xffffffffu, rmax1, 1));
        rmax1 = fmaxf(rmax1, __shfl_xor_sync(0xffffffffu, rmax1, 2));

        float mn0 = fmaxf(m0v, rmax0), mn1 = fmaxf(m1v, rmax1);
        float c0 = __expf(m0v - mn0), c1 = __expf(m1v - mn1);
        m0v = mn0; m1v = mn1;

        float ps0 = 0.f, ps1 = 0.f;
        #pragma unroll
        for (int nt = 0; nt < 8; nt++) {
            s[nt][0] = __expf(s[nt][0] - mn0); ps0 += s[nt][0];
            s[nt][1] = __expf(s[nt][1] - mn0); ps0 += s[nt][1];
            s[nt][2] = __expf(s[nt][2] - mn1); ps1 += s[nt][2];
            s[nt][3] = __expf(s[nt][3] - mn1); ps1 += s[nt][3];
        }
        ps0 += __shfl_xor_sync(0xffffffffu, ps0, 1);
        ps0 += __shfl_xor_sync(0xffffffffu, ps0, 2);
        ps1 += __shfl_xor_sync(0xffffffffu, ps1, 1);
        ps1 += __shfl_xor_sync(0xffffffffu, ps1, 2);
        l0 = l0 * c0 + ps0;
        l1 = l1 * c1 + ps1;

        #pragma unroll
        for (int nt = 0; nt < 8; nt++) {
            acc[nt][0] *= c0; acc[nt][1] *= c0;
            acc[nt][2] *= c1; acc[nt][3] *= c1;
        }

        // P C-frag -> A-frag directly (keys become k of PV mma)
        uint32_t af[4][4];
        #pragma unroll
        for (int kk = 0; kk < 4; kk++) {
            af[kk][0] = pack2(s[2 * kk][0],     s[2 * kk][1]);
            af[kk][1] = pack2(s[2 * kk][2],     s[2 * kk][3]);
            af[kk][2] = pack2(s[2 * kk + 1][0], s[2 * kk + 1][1]);
            af[kk][3] = pack2(s[2 * kk + 1][2], s[2 * kk + 1][3]);
        }

        // acc += P @ V  (B-frags via ldmatrix.trans on raw V)
        #pragma unroll
        for (int np = 0; np < 4; np++) {
            #pragma unroll
            for (int kk = 0; kk < 4; kk++) {
                uint32_t r0, r1, r2, r3;
                ldm_x4_t(r0, r1, r2, r3, vb + (uint32_t)(kk * 16 * 144 + np * 32));
                mma_f16(acc[2*np],   af[kk], r0, r1, acc[2*np]);
                mma_f16(acc[2*np+1], af[kk], r2, r3, acc[2*np+1]);
            }
        }
        __syncthreads();
    }

    const float inv0 = 1.f / l0, inv1 = 1.f / l1;
    const long long o0 = (long long)(b * TT + q0 + g) * EMB + h * SS;
    const long long o1 = (long long)(b * TT + q0 + 8 + g) * EMB + h * SS;
    #pragma unroll
    for (int nt = 0; nt < 8; nt++) {
        *(uint32_t*)(res + o0 + nt * 8 + 2 * t4) = pack2(acc[nt][0] * inv0, acc[nt][1] * inv0);
        *(uint32_t*)(res + o1 + nt * 8 + 2 * t4) = pack2(acc[nt][2] * inv1, acc[nt][3] * inv1);
    }
}

// ---------------- fused residual + LayerNorm (+optional fp16 copy) ------
__global__ __launch_bounds__(256)
void ln_kernel(const float* __restrict__ X, const float* __restrict__ Y,
               const float* __restrict__ g, const float* __restrict__ bta,
               float* __restrict__ out, __half* __restrict__ oh)
{
    const int row = blockIdx.x;
    const int tid = threadIdx.x;
    const float* xr = X + (long long)row * EMB;
    const float* yr = Y + (long long)row * EMB;

    float v[4], s = 0.f, ss = 0.f;
    #pragma unroll
    for (int i = 0; i < 4; i++) {
        int c = tid + i * 256;
        float t = xr[c] + yr[c];
        v[i] = t;
        s += t;
        ss = fmaf(t, t, ss);
    }

    __shared__ float rs[8], rss[8];
    #pragma unroll
    for (int o = 16; o > 0; o >>= 1) {
        s  += __shfl_xor_sync(0xffffffffu, s,  o);
        ss += __shfl_xor_sync(0xffffffffu, ss, o);
    }
    const int warp = tid >> 5, lane = tid & 31;
    if (lane == 0) { rs[warp] = s; rss[warp] = ss; }
    __syncthreads();
    float ts = 0.f, tss = 0.f;
    #pragma unroll
    for (int i = 0; i < 8; i++) { ts += rs[i]; tss += rss[i]; }

    const float mean = ts * (1.0f / EMB);
    const float var  = tss * (1.0f / EMB) - mean * mean;
    const float rstd = rsqrtf(var + 1e-5f);

    #pragma unroll
    for (int i = 0; i < 4; i++) {
        int c = tid + i * 256;
        float o = (v[i] - mean) * rstd * g[c] + bta[c];
        if (out) out[(long long)row * EMB + c] = o;
        if (oh)  oh [(long long)row * EMB + c] = __float2half_rn(o);
    }
}

// ---------------- launch --------------------------------------------------
extern "C" void kernel_launch(void* const* d_in, const int* in_sizes, int n_in,
                              void* d_out, int out_size)
{
    const float* x     = (const float*)d_in[0];
    const float* Wkqv  = (const float*)d_in[1];
    const float* Wproj = (const float*)d_in[2];
    const float* g1    = (const float*)d_in[3];
    const float* b1    = (const float*)d_in[4];
    const float* W1    = (const float*)d_in[5];
    const float* bff1  = (const float*)d_in[6];
    const float* W2    = (const float*)d_in[7];
    const float* bff2  = (const float*)d_in[8];
    const float* g2    = (const float*)d_in[9];
    const float* b2    = (const float*)d_in[10];
    float* out = (float*)d_out;

    float *p_mha, *p_x1, *p_ff;
    __half *p_xh, *p_kqv, *p_res, *p_x1h, *p_hh, *p_Wkh, *p_Wph, *p_W1h, *p_W2h;
    cudaGetSymbolAddress((void**)&p_xh,  g_xh);
    cudaGetSymbolAddress((void**)&p_kqv, g_kqv);
    cudaGetSymbolAddress((void**)&p_res, g_res);
    cudaGetSymbolAddress((void**)&p_mha, g_mha);
    cudaGetSymbolAddress((void**)&p_x1,  g_x1);
    cudaGetSymbolAddress((void**)&p_x1h, g_x1h);
    cudaGetSymbolAddress((void**)&p_hh,  g_hh);
    cudaGetSymbolAddress((void**)&p_ff,  g_ff);
    cudaGetSymbolAddress((void**)&p_Wkh, g_Wkh);
    cudaGetSymbolAddress((void**)&p_Wph, g_Wph);
    cudaGetSymbolAddress((void**)&p_W1h, g_W1h);
    cudaGetSymbolAddress((void**)&p_W2h, g_W2h);

    // smem: 2 stages x (A 18432 + B 64*(BN+8)*2)
    constexpr int SM128 = 2 * (18432 + 64 * 136 * 2);  // 71680
    constexpr int SM64  = 2 * (18432 + 64 * 72  * 2);  // 55296
    cudaFuncSetAttribute(gemm_f16<128,0>, cudaFuncAttributeMaxDynamicSharedMemorySize, SM128);
    cudaFuncSetAttribute(gemm_f16<128,1>, cudaFuncAttributeMaxDynamicSharedMemorySize, SM128);
    cudaFuncSetAttribute(gemm_f16<128,2>, cudaFuncAttributeMaxDynamicSharedMemorySize, SM128);
    cudaFuncSetAttribute(gemm_f16<64,3>,  cudaFuncAttributeMaxDynamicSharedMemorySize, SM64);

    // 0) streaming f32->f16 conversions (all sizes divisible by 1024)
    cvt16<<<(ROWS * EMB) / 1024, 256>>>(x, p_xh);
    cvt16<<<(SS * 192) / 1024, 256>>>(Wkqv, p_Wkh);
    cvt16<<<(EMB * EMB) / 1024, 256>>>(Wproj, p_Wph);
    cvt16<<<(EMB * FF4) / 1024, 256>>>(W1, p_W1h);
    cvt16<<<(FF4 * EMB) / 1024, 256>>>(W2, p_W2h);

    // 1) kqv = xh @ Wkqv : [65536,64] @ [64,192] -> fp16
    gemm_f16<64, 3><<<dim3(192 / 64, (ROWS * HH) / 128), 128, SM64>>>(
        p_xh, p_Wkh, nullptr, nullptr, p_kqv, ROWS * HH, 192, SS);
    // 2) attention -> res (fp16)
    attn_f16<<<dim3(TT / 128, HH, BB), 256>>>(p_kqv, p_res);
    // 3) mha = res @ Wproj
    gemm_f16<128, 0><<<dim3(EMB / 128, ROWS / 128), 128, SM128>>>(
        p_res, p_Wph, nullptr, p_mha, nullptr, ROWS, EMB, EMB);
    // 4) x1 = LN(x + mha)  (+ fp16 copy)
    ln_kernel<<<ROWS, 256>>>(x, p_mha, g1, b1, p_x1, p_x1h);
    // 5) h = gelu(x1 @ W1 + bff1) -> fp16
    gemm_f16<128, 2><<<dim3(FF4 / 128, ROWS / 128), 128, SM128>>>(
        p_x1h, p_W1h, bff1, nullptr, p_hh, ROWS, FF4, EMB);
    // 6) ff = h @ W2 + bff2
    gemm_f16<128, 1><<<dim3(EMB / 128, ROWS / 128), 128, SM128>>>(
        p_hh, p_W2h, bff2, p_ff, nullptr, ROWS, EMB, FF4);
    // 7) out = LN(x1 + ff)
    ln_kernel<<<ROWS, 256>>>(p_x1, p_ff, g2, b2, out, nullptr);
}